// round 2
// baseline (speedup 1.0000x reference)
#include <cuda_runtime.h>
#include <math.h>
#include <stdint.h>

#define B_ 4
#define T_ 1024
#define S_ 1024
#define E_ 1024
#define H_ 16
#define D_ 64
#define MAXLEN 2048

// Scratch (device globals: allocation-free per harness rules).
// Referenced DIRECTLY from device code — no cudaGetSymbolAddress anywhere.
__device__ float g_q[B_ * H_ * T_ * D_];          // [z][t][d], z = b*16+h
__device__ float g_k[B_ * H_ * S_ * D_];          // k_proj + rel folded in
__device__ float g_v[B_ * H_ * S_ * D_];
__device__ float g_s[(size_t)B_ * H_ * T_ * S_];  // scores / attn probs (256 MB)
__device__ float g_ao[B_ * T_ * E_];              // attention out, [B*T, E]

#define BM 128
#define BN 128
#define BK 16

__device__ __forceinline__ float neg_inf() { return __int_as_float(0xff800000); }

// ---------------------------------------------------------------------------
// Projection GEMM: dst = A[4096,1024] @ W[1024,1024]^T + bias (+ rel for K),
// scattered to [z][t][d] layout. WHICH: 0 -> g_q, 1 -> g_k (+rel), 2 -> g_v.
// ---------------------------------------------------------------------------
template <int WHICH>
__global__ __launch_bounds__(256) void proj_gemm(
    const float* __restrict__ A, const float* __restrict__ W,
    const float* __restrict__ bias, const float* __restrict__ rel)
{
    __shared__ float As[BK][BM + 4];
    __shared__ float Bs[BK][BN + 4];

    const int tid = threadIdx.x;
    const int tx = tid & 15;
    const int ty = tid >> 4;
    const int m0 = blockIdx.y * BM;
    const int n0 = blockIdx.x * BN;

    float acc[8][8];
#pragma unroll
    for (int i = 0; i < 8; i++)
#pragma unroll
        for (int j = 0; j < 8; j++) acc[i][j] = 0.0f;

    for (int k0 = 0; k0 < E_; k0 += BK) {
#pragma unroll
        for (int l = 0; l < 2; l++) {
            int idx = tid + l * 256;       // 0..511
            int row = idx >> 2;            // 0..127
            int cf  = idx & 3;
            float4 va = *reinterpret_cast<const float4*>(&A[(size_t)(m0 + row) * E_ + k0 + cf * 4]);
            As[cf * 4 + 0][row] = va.x;
            As[cf * 4 + 1][row] = va.y;
            As[cf * 4 + 2][row] = va.z;
            As[cf * 4 + 3][row] = va.w;
            float4 vb = *reinterpret_cast<const float4*>(&W[(size_t)(n0 + row) * E_ + k0 + cf * 4]);
            Bs[cf * 4 + 0][row] = vb.x;
            Bs[cf * 4 + 1][row] = vb.y;
            Bs[cf * 4 + 2][row] = vb.z;
            Bs[cf * 4 + 3][row] = vb.w;
        }
        __syncthreads();

#pragma unroll
        for (int kk = 0; kk < BK; kk++) {
            float4 a0 = *reinterpret_cast<const float4*>(&As[kk][ty * 8]);
            float4 a1 = *reinterpret_cast<const float4*>(&As[kk][ty * 8 + 4]);
            float4 b0 = *reinterpret_cast<const float4*>(&Bs[kk][tx * 8]);
            float4 b1 = *reinterpret_cast<const float4*>(&Bs[kk][tx * 8 + 4]);
            float a[8] = {a0.x, a0.y, a0.z, a0.w, a1.x, a1.y, a1.z, a1.w};
            float b[8] = {b0.x, b0.y, b0.z, b0.w, b1.x, b1.y, b1.z, b1.w};
#pragma unroll
            for (int i = 0; i < 8; i++)
#pragma unroll
                for (int j = 0; j < 8; j++) acc[i][j] = fmaf(a[i], b[j], acc[i][j]);
        }
        __syncthreads();
    }

    float* dst = (WHICH == 0) ? g_q : (WHICH == 1) ? g_k : g_v;
#pragma unroll
    for (int i = 0; i < 8; i++) {
        int m = m0 + ty * 8 + i;
        int bb = m >> 10, t = m & 1023;
#pragma unroll
        for (int j = 0; j < 8; j++) {
            int n = n0 + tx * 8 + j;
            float v = acc[i][j] + bias[n];
            int h = n >> 6, d = n & 63;
            if constexpr (WHICH == 1) v += rel[((size_t)h * MAXLEN + t) * D_ + d];
            dst[((size_t)(bb * H_ + h) * T_ + t) * D_ + d] = v;
        }
    }
}

// ---------------------------------------------------------------------------
// Scores: g_s[z] = g_q[z] (T x D) @ g_k[z]^T (S x D), masked. z = blockIdx.z.
// ---------------------------------------------------------------------------
__global__ __launch_bounds__(256) void scores_gemm(const unsigned char* __restrict__ mask)
{
    __shared__ float As[BK][BM + 4];
    __shared__ float Bs[BK][BN + 4];

    const int tid = threadIdx.x;
    const int tx = tid & 15;
    const int ty = tid >> 4;
    const int m0 = blockIdx.y * BM;
    const int n0 = blockIdx.x * BN;
    const int z  = blockIdx.z;
    const float* A  = g_q + (size_t)z * T_ * D_;
    const float* Bw = g_k + (size_t)z * S_ * D_;

    float acc[8][8];
#pragma unroll
    for (int i = 0; i < 8; i++)
#pragma unroll
        for (int j = 0; j < 8; j++) acc[i][j] = 0.0f;

    for (int k0 = 0; k0 < D_; k0 += BK) {
#pragma unroll
        for (int l = 0; l < 2; l++) {
            int idx = tid + l * 256;
            int row = idx >> 2;
            int cf  = idx & 3;
            float4 va = *reinterpret_cast<const float4*>(&A[(size_t)(m0 + row) * D_ + k0 + cf * 4]);
            As[cf * 4 + 0][row] = va.x;
            As[cf * 4 + 1][row] = va.y;
            As[cf * 4 + 2][row] = va.z;
            As[cf * 4 + 3][row] = va.w;
            float4 vb = *reinterpret_cast<const float4*>(&Bw[(size_t)(n0 + row) * D_ + k0 + cf * 4]);
            Bs[cf * 4 + 0][row] = vb.x;
            Bs[cf * 4 + 1][row] = vb.y;
            Bs[cf * 4 + 2][row] = vb.z;
            Bs[cf * 4 + 3][row] = vb.w;
        }
        __syncthreads();

#pragma unroll
        for (int kk = 0; kk < BK; kk++) {
            float4 a0 = *reinterpret_cast<const float4*>(&As[kk][ty * 8]);
            float4 a1 = *reinterpret_cast<const float4*>(&As[kk][ty * 8 + 4]);
            float4 b0 = *reinterpret_cast<const float4*>(&Bs[kk][tx * 8]);
            float4 b1 = *reinterpret_cast<const float4*>(&Bs[kk][tx * 8 + 4]);
            float a[8] = {a0.x, a0.y, a0.z, a0.w, a1.x, a1.y, a1.z, a1.w};
            float b[8] = {b0.x, b0.y, b0.z, b0.w, b1.x, b1.y, b1.z, b1.w};
#pragma unroll
            for (int i = 0; i < 8; i++)
#pragma unroll
                for (int j = 0; j < 8; j++) acc[i][j] = fmaf(a[i], b[j], acc[i][j]);
        }
        __syncthreads();
    }

    const int bb = z >> 4;
#pragma unroll
    for (int i = 0; i < 8; i++) {
        int m = m0 + ty * 8 + i;
#pragma unroll
        for (int j = 0; j < 8; j++) {
            int n = n0 + tx * 8 + j;
            float v = acc[i][j];
            if (mask[bb * S_ + n]) v = neg_inf();
            g_s[((size_t)z * T_ + m) * S_ + n] = v;
        }
    }
}

// ---------------------------------------------------------------------------
// Row softmax over S=1024. One block (256 thr) per row of g_s.
// ---------------------------------------------------------------------------
__global__ __launch_bounds__(256) void softmax_k()
{
    const size_t row = blockIdx.x;           // z*T + t
    float* p = g_s + row * S_;
    const int tid = threadIdx.x;

    float4 v = reinterpret_cast<float4*>(p)[tid];

    __shared__ float red[8];
    float mx = fmaxf(fmaxf(v.x, v.y), fmaxf(v.z, v.w));
#pragma unroll
    for (int o = 16; o; o >>= 1) mx = fmaxf(mx, __shfl_xor_sync(0xffffffffu, mx, o));
    if ((tid & 31) == 0) red[tid >> 5] = mx;
    __syncthreads();
    float m8 = red[0];
#pragma unroll
    for (int i = 1; i < 8; i++) m8 = fmaxf(m8, red[i]);
    __syncthreads();

    // exp(-inf - m8) = 0 handles masked entries naturally (m8 finite unless all masked)
    v.x = __expf(v.x - m8);
    v.y = __expf(v.y - m8);
    v.z = __expf(v.z - m8);
    v.w = __expf(v.w - m8);
    float sm = v.x + v.y + v.z + v.w;
#pragma unroll
    for (int o = 16; o; o >>= 1) sm += __shfl_xor_sync(0xffffffffu, sm, o);
    if ((tid & 31) == 0) red[tid >> 5] = sm;
    __syncthreads();
    float s8 = red[0];
#pragma unroll
    for (int i = 1; i < 8; i++) s8 += red[i];
    float inv = __frcp_rn(s8);

    v.x *= inv; v.y *= inv; v.z *= inv; v.w *= inv;
    reinterpret_cast<float4*>(p)[tid] = v;
}

// ---------------------------------------------------------------------------
// PV: g_ao[b*T+t][h*64+d] = g_s[z] (T x S) @ g_v[z] (S x D)
// ---------------------------------------------------------------------------
__global__ __launch_bounds__(256) void pv_k()
{
    __shared__ float As[BK][BM + 4];
    __shared__ float Bs[BK][D_ + 4];

    const int tid = threadIdx.x;
    const int tx = tid & 15;
    const int ty = tid >> 4;
    const int m0 = blockIdx.y * BM;
    const int z  = blockIdx.z;
    const float* Az = g_s + (size_t)z * T_ * S_;
    const float* Vz = g_v + (size_t)z * S_ * D_;

    float acc[8][4];
#pragma unroll
    for (int i = 0; i < 8; i++)
#pragma unroll
        for (int j = 0; j < 4; j++) acc[i][j] = 0.0f;

    for (int k0 = 0; k0 < S_; k0 += BK) {
#pragma unroll
        for (int l = 0; l < 2; l++) {
            int idx = tid + l * 256;
            int row = idx >> 2;
            int cf  = idx & 3;
            float4 va = *reinterpret_cast<const float4*>(&Az[(size_t)(m0 + row) * S_ + k0 + cf * 4]);
            As[cf * 4 + 0][row] = va.x;
            As[cf * 4 + 1][row] = va.y;
            As[cf * 4 + 2][row] = va.z;
            As[cf * 4 + 3][row] = va.w;
        }
        {
            int row = tid >> 4;            // 0..15
            int cf  = tid & 15;            // 0..15 -> 64 cols
            float4 vb = *reinterpret_cast<const float4*>(&Vz[(size_t)(k0 + row) * D_ + cf * 4]);
            *reinterpret_cast<float4*>(&Bs[row][cf * 4]) = vb;
        }
        __syncthreads();

#pragma unroll
        for (int kk = 0; kk < BK; kk++) {
            float4 a0 = *reinterpret_cast<const float4*>(&As[kk][ty * 8]);
            float4 a1 = *reinterpret_cast<const float4*>(&As[kk][ty * 8 + 4]);
            float4 b0 = *reinterpret_cast<const float4*>(&Bs[kk][tx * 4]);
            float a[8] = {a0.x, a0.y, a0.z, a0.w, a1.x, a1.y, a1.z, a1.w};
            float b[4] = {b0.x, b0.y, b0.z, b0.w};
#pragma unroll
            for (int i = 0; i < 8; i++)
#pragma unroll
                for (int j = 0; j < 4; j++) acc[i][j] = fmaf(a[i], b[j], acc[i][j]);
        }
        __syncthreads();
    }

    const int bb = z >> 4, h = z & 15;
#pragma unroll
    for (int i = 0; i < 8; i++) {
        int t = m0 + ty * 8 + i;
#pragma unroll
        for (int j = 0; j < 4; j++) {
            int d = tx * 4 + j;
            g_ao[((size_t)(bb * T_ + t)) * E_ + h * D_ + d] = acc[i][j];
        }
    }
}

// ---------------------------------------------------------------------------
// Output projection: out = g_ao[4096,1024] @ o_w^T + o_b
// ---------------------------------------------------------------------------
__global__ __launch_bounds__(256) void out_gemm(
    const float* __restrict__ W, const float* __restrict__ bias,
    float* __restrict__ out)
{
    __shared__ float As[BK][BM + 4];
    __shared__ float Bs[BK][BN + 4];

    const int tid = threadIdx.x;
    const int tx = tid & 15;
    const int ty = tid >> 4;
    const int m0 = blockIdx.y * BM;
    const int n0 = blockIdx.x * BN;

    float acc[8][8];
#pragma unroll
    for (int i = 0; i < 8; i++)
#pragma unroll
        for (int j = 0; j < 8; j++) acc[i][j] = 0.0f;

    for (int k0 = 0; k0 < E_; k0 += BK) {
#pragma unroll
        for (int l = 0; l < 2; l++) {
            int idx = tid + l * 256;
            int row = idx >> 2;
            int cf  = idx & 3;
            float4 va = *reinterpret_cast<const float4*>(&g_ao[(size_t)(m0 + row) * E_ + k0 + cf * 4]);
            As[cf * 4 + 0][row] = va.x;
            As[cf * 4 + 1][row] = va.y;
            As[cf * 4 + 2][row] = va.z;
            As[cf * 4 + 3][row] = va.w;
            float4 vb = *reinterpret_cast<const float4*>(&W[(size_t)(n0 + row) * E_ + k0 + cf * 4]);
            Bs[cf * 4 + 0][row] = vb.x;
            Bs[cf * 4 + 1][row] = vb.y;
            Bs[cf * 4 + 2][row] = vb.z;
            Bs[cf * 4 + 3][row] = vb.w;
        }
        __syncthreads();

#pragma unroll
        for (int kk = 0; kk < BK; kk++) {
            float4 a0 = *reinterpret_cast<const float4*>(&As[kk][ty * 8]);
            float4 a1 = *reinterpret_cast<const float4*>(&As[kk][ty * 8 + 4]);
            float4 b0 = *reinterpret_cast<const float4*>(&Bs[kk][tx * 8]);
            float4 b1 = *reinterpret_cast<const float4*>(&Bs[kk][tx * 8 + 4]);
            float a[8] = {a0.x, a0.y, a0.z, a0.w, a1.x, a1.y, a1.z, a1.w};
            float b[8] = {b0.x, b0.y, b0.z, b0.w, b1.x, b1.y, b1.z, b1.w};
#pragma unroll
            for (int i = 0; i < 8; i++)
#pragma unroll
                for (int j = 0; j < 8; j++) acc[i][j] = fmaf(a[i], b[j], acc[i][j]);
        }
        __syncthreads();
    }

#pragma unroll
    for (int i = 0; i < 8; i++) {
        int m = m0 + ty * 8 + i;
#pragma unroll
        for (int j = 0; j < 8; j++) {
            int n = n0 + tx * 8 + j;
            out[(size_t)m * E_ + n] = acc[i][j] + bias[n];
        }
    }
}

extern "C" void kernel_launch(void* const* d_in, const int* in_sizes, int n_in,
                              void* d_out, int out_size)
{
    const float* query = (const float*)d_in[0];
    const float* key   = (const float*)d_in[1];
    const float* value = (const float*)d_in[2];
    const unsigned char* mask = (const unsigned char*)d_in[3];
    const float* q_w = (const float*)d_in[4];
    const float* q_b = (const float*)d_in[5];
    const float* k_w = (const float*)d_in[6];
    const float* k_b = (const float*)d_in[7];
    const float* v_w = (const float*)d_in[8];
    const float* v_b = (const float*)d_in[9];
    const float* o_w = (const float*)d_in[10];
    const float* o_b = (const float*)d_in[11];
    const float* rel = (const float*)d_in[12];
    float* out = (float*)d_out;

    const int M = B_ * T_;   // 4096

    dim3 pg(E_ / BN, M / BM, 1);
    proj_gemm<0><<<pg, 256>>>(query, q_w, q_b, nullptr);
    proj_gemm<1><<<pg, 256>>>(key,   k_w, k_b, rel);
    proj_gemm<2><<<pg, 256>>>(value, v_w, v_b, nullptr);

    dim3 sg(S_ / BN, T_ / BM, B_ * H_);
    scores_gemm<<<sg, 256>>>(mask);

    softmax_k<<<B_ * H_ * T_, 256>>>();

    dim3 vg(1, T_ / BM, B_ * H_);
    pv_k<<<vg, 256>>>();

    dim3 og(E_ / BN, M / BM, 1);
    out_gemm<<<og, 256>>>(o_w, o_b, out);
}

// round 5
// speedup vs baseline: 1.4899x; 1.4899x over previous
#include <cuda_runtime.h>
#include <cuda_bf16.h>
#include <math.h>
#include <stdint.h>

#define B_ 4
#define T_ 1024
#define S_ 1024
#define E_ 1024
#define H_ 16
#define D_ 64
#define MAXLEN 2048

// Scratch (device globals; referenced ONLY from device code)
__device__ float g_q[B_ * H_ * T_ * D_];          // [z][t][d], z = b*16+h
__device__ float g_k[B_ * H_ * S_ * D_];          // k_proj + rel folded in
__device__ float g_v[B_ * H_ * S_ * D_];
__device__ float g_s[(size_t)B_ * H_ * T_ * S_];  // scores / attn probs
__device__ float g_ao[B_ * T_ * E_];              // attention out, [B*T, E]

#define BK 32      // k per smem tile (fp32 elements) = 16 bf16-pairs
#define PP 20      // smem row stride in pair-words (16 + 4 pad, conflict-free)

__device__ __forceinline__ float neg_inf() { return __int_as_float(0xff800000); }

// Split two fp32 into packed bf16 hi/lo pair-words (low half = even-k element).
__device__ __forceinline__ void split2(float x, float y, uint32_t& hi, uint32_t& lo) {
    __nv_bfloat16 xh = __float2bfloat16(x);
    __nv_bfloat16 yh = __float2bfloat16(y);
    __nv_bfloat16 xl = __float2bfloat16(x - __bfloat162float(xh));
    __nv_bfloat16 yl = __float2bfloat16(y - __bfloat162float(yh));
    hi = (uint32_t)__bfloat16_as_ushort(xh) | ((uint32_t)__bfloat16_as_ushort(yh) << 16);
    lo = (uint32_t)__bfloat16_as_ushort(xl) | ((uint32_t)__bfloat16_as_ushort(yl) << 16);
}

__device__ __forceinline__ void mma_bf16(float c[4], const uint32_t a[4], const uint32_t b[2]) {
    asm volatile(
        "mma.sync.aligned.m16n8k16.row.col.f32.bf16.bf16.f32 "
        "{%0,%1,%2,%3}, {%4,%5,%6,%7}, {%8,%9}, {%0,%1,%2,%3};"
        : "+f"(c[0]), "+f"(c[1]), "+f"(c[2]), "+f"(c[3])
        : "r"(a[0]), "r"(a[1]), "r"(a[2]), "r"(a[3]), "r"(b[0]), "r"(b[1]));
}

// ---------------------------------------------------------------------------
// 128x128 NT GEMM, bf16x3 split: C = A[M,K] @ B[N,K]^T (fp32-accurate).
// EPI 0/1/2: Q/K/V projection -> g_q/g_k/g_v scatter (+bias, +rel for K)
// EPI 3: scores (batched, z=blockIdx.z): g_q[z] @ g_k[z]^T + mask -> g_s
// EPI 4: O proj: g_ao @ W^T + bias -> out
// ---------------------------------------------------------------------------
template <int EPI>
__global__ __launch_bounds__(256) void gemm_b3(
    const float* __restrict__ A_in, const float* __restrict__ Bw_in,
    const float* __restrict__ bias, const float* __restrict__ rel,
    const unsigned char* __restrict__ mask, float* __restrict__ out, int K)
{
    __shared__ uint32_t As_hi[128][PP], As_lo[128][PP];
    __shared__ uint32_t Bs_hi[128][PP], Bs_lo[128][PP];

    const int tid = threadIdx.x;
    const int m0 = blockIdx.y * 128;
    const int n0 = blockIdx.x * 128;
    const int z  = blockIdx.z;

    const float* A  = (EPI == 3) ? (g_q + (size_t)z * T_ * D_)
                    : (EPI == 4) ? g_ao : A_in;
    const float* Bw = (EPI == 3) ? (g_k + (size_t)z * S_ * D_) : Bw_in;

    const int lane = tid & 31, warp = tid >> 5;
    const int wy = warp >> 2, wx = warp & 3;      // 2x4 warp grid: 64x32 per warp
    const int grp = lane >> 2, tig = lane & 3;

    float acc[4][4][4];
#pragma unroll
    for (int i = 0; i < 4; i++)
#pragma unroll
        for (int j = 0; j < 4; j++)
#pragma unroll
            for (int r = 0; r < 4; r++) acc[i][j][r] = 0.0f;

    for (int k0 = 0; k0 < K; k0 += BK) {
        // Fill smem: 128x32 fp32 -> split bf16 pairs. 1024 float4/tile, 4/thread.
#pragma unroll
        for (int l = 0; l < 4; l++) {
            int idx = tid + l * 256;
            int row = idx >> 3, c4 = idx & 7;       // c4 -> pair cols c4*2, c4*2+1
            float4 va = *reinterpret_cast<const float4*>(&A[(size_t)(m0 + row) * K + k0 + c4 * 4]);
            uint32_t h0, l0, h1, l1;
            split2(va.x, va.y, h0, l0);
            split2(va.z, va.w, h1, l1);
            As_hi[row][c4 * 2] = h0; As_hi[row][c4 * 2 + 1] = h1;
            As_lo[row][c4 * 2] = l0; As_lo[row][c4 * 2 + 1] = l1;
            float4 vb = *reinterpret_cast<const float4*>(&Bw[(size_t)(n0 + row) * K + k0 + c4 * 4]);
            split2(vb.x, vb.y, h0, l0);
            split2(vb.z, vb.w, h1, l1);
            Bs_hi[row][c4 * 2] = h0; Bs_hi[row][c4 * 2 + 1] = h1;
            Bs_lo[row][c4 * 2] = l0; Bs_lo[row][c4 * 2 + 1] = l1;
        }
        __syncthreads();

#pragma unroll
        for (int ks = 0; ks < 2; ks++) {           // two k=16 steps
            const int kb = ks * 8;                 // pair offset
            uint32_t ah[4][4], al[4][4], bh[4][2], bl[4][2];
#pragma unroll
            for (int i = 0; i < 4; i++) {
                int r0 = wy * 64 + i * 16 + grp;
                ah[i][0] = As_hi[r0][kb + tig];
                ah[i][1] = As_hi[r0 + 8][kb + tig];
                ah[i][2] = As_hi[r0][kb + tig + 4];
                ah[i][3] = As_hi[r0 + 8][kb + tig + 4];
                al[i][0] = As_lo[r0][kb + tig];
                al[i][1] = As_lo[r0 + 8][kb + tig];
                al[i][2] = As_lo[r0][kb + tig + 4];
                al[i][3] = As_lo[r0 + 8][kb + tig + 4];
            }
#pragma unroll
            for (int j = 0; j < 4; j++) {
                int c0 = wx * 32 + j * 8 + grp;
                bh[j][0] = Bs_hi[c0][kb + tig];
                bh[j][1] = Bs_hi[c0][kb + tig + 4];
                bl[j][0] = Bs_lo[c0][kb + tig];
                bl[j][1] = Bs_lo[c0][kb + tig + 4];
            }
#pragma unroll
            for (int i = 0; i < 4; i++)
#pragma unroll
                for (int j = 0; j < 4; j++) {
                    mma_bf16(acc[i][j], ah[i], bh[j]);
                    mma_bf16(acc[i][j], al[i], bh[j]);
                    mma_bf16(acc[i][j], ah[i], bl[j]);
                }
        }
        __syncthreads();
    }

    // Epilogue
#pragma unroll
    for (int i = 0; i < 4; i++) {
#pragma unroll
        for (int j = 0; j < 4; j++) {
#pragma unroll
            for (int r = 0; r < 4; r++) {
                int m = m0 + wy * 64 + i * 16 + grp + ((r & 2) ? 8 : 0);
                int n = n0 + wx * 32 + j * 8 + 2 * tig + (r & 1);
                float v = acc[i][j][r];
                if constexpr (EPI <= 2) {
                    v += bias[n];
                    int bb = m >> 10, t = m & 1023;
                    int h = n >> 6, d = n & 63;
                    if constexpr (EPI == 1) v += rel[((size_t)h * MAXLEN + t) * D_ + d];
                    float* dst = (EPI == 0) ? g_q : (EPI == 1) ? g_k : g_v;
                    dst[((size_t)(bb * H_ + h) * T_ + t) * D_ + d] = v;
                } else if constexpr (EPI == 3) {
                    if (mask[(z >> 4) * S_ + n]) v = neg_inf();
                    g_s[((size_t)z * T_ + m) * S_ + n] = v;
                } else {
                    out[(size_t)m * E_ + n] = v + bias[n];
                }
            }
        }
    }
}

// ---------------------------------------------------------------------------
// Row softmax over S=1024. One block (256 thr) per row of g_s.
// ---------------------------------------------------------------------------
__global__ __launch_bounds__(256) void softmax_k()
{
    const size_t row = blockIdx.x;
    float* p = g_s + row * S_;
    const int tid = threadIdx.x;

    float4 v = reinterpret_cast<float4*>(p)[tid];

    __shared__ float red[8];
    float mx = fmaxf(fmaxf(v.x, v.y), fmaxf(v.z, v.w));
#pragma unroll
    for (int o = 16; o; o >>= 1) mx = fmaxf(mx, __shfl_xor_sync(0xffffffffu, mx, o));
    if ((tid & 31) == 0) red[tid >> 5] = mx;
    __syncthreads();
    float m8 = red[0];
#pragma unroll
    for (int i = 1; i < 8; i++) m8 = fmaxf(m8, red[i]);
    __syncthreads();

    v.x = __expf(v.x - m8);
    v.y = __expf(v.y - m8);
    v.z = __expf(v.z - m8);
    v.w = __expf(v.w - m8);
    float sm = v.x + v.y + v.z + v.w;
#pragma unroll
    for (int o = 16; o; o >>= 1) sm += __shfl_xor_sync(0xffffffffu, sm, o);
    if ((tid & 31) == 0) red[tid >> 5] = sm;
    __syncthreads();
    float s8 = red[0];
#pragma unroll
    for (int i = 1; i < 8; i++) s8 += red[i];
    float inv = __frcp_rn(s8);

    v.x *= inv; v.y *= inv; v.z *= inv; v.w *= inv;
    reinterpret_cast<float4*>(p)[tid] = v;
}

// ---------------------------------------------------------------------------
// PV (NN): g_ao[b*T+t][h*64+d] = g_s[z] (T x S) @ g_v[z] (S x 64), bf16x3.
// 128x64 tile, BK=32. Warps 4x2: each warp 32 rows x 32 cols.
// ---------------------------------------------------------------------------
__global__ __launch_bounds__(256) void pv_b3()
{
    __shared__ uint32_t As_hi[128][PP], As_lo[128][PP];
    __shared__ uint32_t Bs_hi[64][PP],  Bs_lo[64][PP];

    const int tid = threadIdx.x;
    const int m0 = blockIdx.y * 128;
    const int z  = blockIdx.z;
    const float* Az = g_s + (size_t)z * T_ * S_;
    const float* Vz = g_v + (size_t)z * S_ * D_;

    const int lane = tid & 31, warp = tid >> 5;
    const int wy = warp >> 1, wx = warp & 1;      // 4x2 warp grid: 32x32 per warp
    const int grp = lane >> 2, tig = lane & 3;

    float acc[2][4][4];
#pragma unroll
    for (int i = 0; i < 2; i++)
#pragma unroll
        for (int j = 0; j < 4; j++)
#pragma unroll
            for (int r = 0; r < 4; r++) acc[i][j][r] = 0.0f;

    for (int k0 = 0; k0 < S_; k0 += BK) {
        // A: 128x32 probs -> split pairs
#pragma unroll
        for (int l = 0; l < 4; l++) {
            int idx = tid + l * 256;
            int row = idx >> 3, c4 = idx & 7;
            float4 va = *reinterpret_cast<const float4*>(&Az[(size_t)(m0 + row) * S_ + k0 + c4 * 4]);
            uint32_t h0, l0, h1, l1;
            split2(va.x, va.y, h0, l0);
            split2(va.z, va.w, h1, l1);
            As_hi[row][c4 * 2] = h0; As_hi[row][c4 * 2 + 1] = h1;
            As_lo[row][c4 * 2] = l0; As_lo[row][c4 * 2 + 1] = l1;
        }
        // B: V[k0..k0+32][0..64] transposed into Bs[n][k_pair].
        // Thread -> (pair p = tid>>4, n-group n4 = tid&15); loads rows 2p, 2p+1.
        {
            int p  = tid >> 4;
            int n4 = tid & 15;
            float4 v0 = *reinterpret_cast<const float4*>(&Vz[(size_t)(k0 + 2 * p) * D_ + n4 * 4]);
            float4 v1 = *reinterpret_cast<const float4*>(&Vz[(size_t)(k0 + 2 * p + 1) * D_ + n4 * 4]);
            const float e0[4] = { v0.x, v0.y, v0.z, v0.w };
            const float e1[4] = { v1.x, v1.y, v1.z, v1.w };
#pragma unroll
            for (int e = 0; e < 4; e++) {
                uint32_t h, lo;
                split2(e0[e], e1[e], h, lo);       // (k even, k odd) pair
                Bs_hi[n4 * 4 + e][p] = h;
                Bs_lo[n4 * 4 + e][p] = lo;
            }
        }
        __syncthreads();

#pragma unroll
        for (int ks = 0; ks < 2; ks++) {
            const int kb = ks * 8;
            uint32_t ah[2][4], al[2][4], bh[4][2], bl[4][2];
#pragma unroll
            for (int i = 0; i < 2; i++) {
                int r0 = wy * 32 + i * 16 + grp;
                ah[i][0] = As_hi[r0][kb + tig];
                ah[i][1] = As_hi[r0 + 8][kb + tig];
                ah[i][2] = As_hi[r0][kb + tig + 4];
                ah[i][3] = As_hi[r0 + 8][kb + tig + 4];
                al[i][0] = As_lo[r0][kb + tig];
                al[i][1] = As_lo[r0 + 8][kb + tig];
                al[i][2] = As_lo[r0][kb + tig + 4];
                al[i][3] = As_lo[r0 + 8][kb + tig + 4];
            }
#pragma unroll
            for (int j = 0; j < 4; j++) {
                int c0 = wx * 32 + j * 8 + grp;
                bh[j][0] = Bs_hi[c0][kb + tig];
                bh[j][1] = Bs_hi[c0][kb + tig + 4];
                bl[j][0] = Bs_lo[c0][kb + tig];
                bl[j][1] = Bs_lo[c0][kb + tig + 4];
            }
#pragma unroll
            for (int i = 0; i < 2; i++)
#pragma unroll
                for (int j = 0; j < 4; j++) {
                    mma_bf16(acc[i][j], ah[i], bh[j]);
                    mma_bf16(acc[i][j], al[i], bh[j]);
                    mma_bf16(acc[i][j], ah[i], bl[j]);
                }
        }
        __syncthreads();
    }

    const int bb = z >> 4, h = z & 15;
#pragma unroll
    for (int i = 0; i < 2; i++)
#pragma unroll
        for (int j = 0; j < 4; j++)
#pragma unroll
            for (int r = 0; r < 4; r++) {
                int t = m0 + wy * 32 + i * 16 + grp + ((r & 2) ? 8 : 0);
                int d = wx * 32 + j * 8 + 2 * tig + (r & 1);
                g_ao[((size_t)(bb * T_ + t)) * E_ + h * D_ + d] = acc[i][j][r];
            }
}

extern "C" void kernel_launch(void* const* d_in, const int* in_sizes, int n_in,
                              void* d_out, int out_size)
{
    const float* query = (const float*)d_in[0];
    const float* key   = (const float*)d_in[1];
    const float* value = (const float*)d_in[2];
    const unsigned char* mask = (const unsigned char*)d_in[3];
    const float* q_w = (const float*)d_in[4];
    const float* q_b = (const float*)d_in[5];
    const float* k_w = (const float*)d_in[6];
    const float* k_b = (const float*)d_in[7];
    const float* v_w = (const float*)d_in[8];
    const float* v_b = (const float*)d_in[9];
    const float* o_w = (const float*)d_in[10];
    const float* o_b = (const float*)d_in[11];
    const float* rel = (const float*)d_in[12];
    float* out = (float*)d_out;

    dim3 pg(E_ / 128, (B_ * T_) / 128, 1);
    gemm_b3<0><<<pg, 256>>>(query, q_w, q_b, nullptr, nullptr, nullptr, E_);
    gemm_b3<1><<<pg, 256>>>(key,   k_w, k_b, rel,     nullptr, nullptr, E_);
    gemm_b3<2><<<pg, 256>>>(value, v_w, v_b, nullptr, nullptr, nullptr, E_);

    dim3 sg(S_ / 128, T_ / 128, B_ * H_);
    gemm_b3<3><<<sg, 256>>>(nullptr, nullptr, nullptr, nullptr, mask, nullptr, D_);

    softmax_k<<<B_ * H_ * T_, 256>>>();

    dim3 vg(1, T_ / 128, B_ * H_);
    pv_b3<<<vg, 256>>>();

    dim3 og(E_ / 128, (B_ * T_) / 128, 1);
    gemm_b3<4><<<og, 256>>>(nullptr, o_w, o_b, nullptr, nullptr, out, E_);
}

// round 6
// speedup vs baseline: 2.0375x; 1.3676x over previous
#include <cuda_runtime.h>
#include <cuda_bf16.h>
#include <math.h>
#include <stdint.h>

#define B_ 4
#define T_ 1024
#define S_ 1024
#define E_ 1024
#define H_ 16
#define D_ 64
#define MAXLEN 2048

// Scratch (device globals; referenced ONLY from device code)
__device__ float g_q[B_ * H_ * T_ * D_];          // [z][t][d], z = b*16+h
__device__ float g_k[B_ * H_ * S_ * D_];          // k_proj + rel folded in
__device__ float g_v[B_ * H_ * S_ * D_];
__device__ float g_s[(size_t)B_ * H_ * T_ * S_];  // scores / attn probs
__device__ float g_ao[B_ * T_ * E_];              // attention out, [B*T, E]

#define BK 32      // k per smem tile (fp32 elements) = 16 bf16-pairs
#define PP 20      // smem row stride in pair-words (16 + 4 pad, conflict-free)

__device__ __forceinline__ float neg_inf() { return __int_as_float(0xff800000); }

// Split two fp32 into packed bf16 hi/lo pair-words (low half = even-k element).
__device__ __forceinline__ void split2(float x, float y, uint32_t& hi, uint32_t& lo) {
    __nv_bfloat16 xh = __float2bfloat16(x);
    __nv_bfloat16 yh = __float2bfloat16(y);
    __nv_bfloat16 xl = __float2bfloat16(x - __bfloat162float(xh));
    __nv_bfloat16 yl = __float2bfloat16(y - __bfloat162float(yh));
    hi = (uint32_t)__bfloat16_as_ushort(xh) | ((uint32_t)__bfloat16_as_ushort(yh) << 16);
    lo = (uint32_t)__bfloat16_as_ushort(xl) | ((uint32_t)__bfloat16_as_ushort(yl) << 16);
}

__device__ __forceinline__ void mma_bf16(float c[4], const uint32_t a[4], const uint32_t b[2]) {
    asm volatile(
        "mma.sync.aligned.m16n8k16.row.col.f32.bf16.bf16.f32 "
        "{%0,%1,%2,%3}, {%4,%5,%6,%7}, {%8,%9}, {%0,%1,%2,%3};"
        : "+f"(c[0]), "+f"(c[1]), "+f"(c[2]), "+f"(c[3])
        : "r"(a[0]), "r"(a[1]), "r"(a[2]), "r"(a[3]), "r"(b[0]), "r"(b[1]));
}

// ---------------------------------------------------------------------------
// 128x128 NT GEMM, bf16x3 split: C = A[M,K] @ B[N,K]^T (fp32-accurate).
// EPI 0/1/2: Q/K/V projection -> g_q/g_k/g_v scatter (+bias, +rel for K)
// EPI 3: scores (batched, z=blockIdx.z): g_q[z] @ g_k[z]^T + mask -> g_s
// EPI 4: O proj: g_ao @ W^T + bias -> out
// ---------------------------------------------------------------------------
template <int EPI>
__global__ __launch_bounds__(256, 2) void gemm_b3(
    const float* __restrict__ A_in, const float* __restrict__ Bw_in,
    const float* __restrict__ bias, const float* __restrict__ rel,
    const unsigned char* __restrict__ mask, float* __restrict__ out, int K)
{
    __shared__ uint32_t As_hi[128][PP], As_lo[128][PP];
    __shared__ uint32_t Bs_hi[128][PP], Bs_lo[128][PP];

    const int tid = threadIdx.x;
    const int m0 = blockIdx.y * 128;
    const int n0 = blockIdx.x * 128;
    const int z  = blockIdx.z;

    const float* A  = (EPI == 3) ? (g_q + (size_t)z * T_ * D_)
                    : (EPI == 4) ? g_ao : A_in;
    const float* Bw = (EPI == 3) ? (g_k + (size_t)z * S_ * D_) : Bw_in;

    const int lane = tid & 31, warp = tid >> 5;
    const int wy = warp >> 2, wx = warp & 3;      // 2x4 warp grid: 64x32 per warp
    const int grp = lane >> 2, tig = lane & 3;

    float acc[4][4][4];
#pragma unroll
    for (int i = 0; i < 4; i++)
#pragma unroll
        for (int j = 0; j < 4; j++)
#pragma unroll
            for (int r = 0; r < 4; r++) acc[i][j][r] = 0.0f;

    for (int k0 = 0; k0 < K; k0 += BK) {
        // Fill smem: 128x32 fp32 -> split bf16 pairs. 1024 float4/tile, 4/thread.
#pragma unroll
        for (int l = 0; l < 4; l++) {
            int idx = tid + l * 256;
            int row = idx >> 3, c4 = idx & 7;       // c4 -> pair cols c4*2, c4*2+1
            float4 va = *reinterpret_cast<const float4*>(&A[(size_t)(m0 + row) * K + k0 + c4 * 4]);
            uint32_t h0, l0, h1, l1;
            split2(va.x, va.y, h0, l0);
            split2(va.z, va.w, h1, l1);
            As_hi[row][c4 * 2] = h0; As_hi[row][c4 * 2 + 1] = h1;
            As_lo[row][c4 * 2] = l0; As_lo[row][c4 * 2 + 1] = l1;
            float4 vb = *reinterpret_cast<const float4*>(&Bw[(size_t)(n0 + row) * K + k0 + c4 * 4]);
            split2(vb.x, vb.y, h0, l0);
            split2(vb.z, vb.w, h1, l1);
            Bs_hi[row][c4 * 2] = h0; Bs_hi[row][c4 * 2 + 1] = h1;
            Bs_lo[row][c4 * 2] = l0; Bs_lo[row][c4 * 2 + 1] = l1;
        }
        __syncthreads();

#pragma unroll
        for (int ks = 0; ks < 2; ks++) {           // two k=16 steps
            const int kb = ks * 8;                 // pair offset
            // B fragments resident for the whole k-step (16 regs)
            uint32_t bh[4][2], bl[4][2];
#pragma unroll
            for (int j = 0; j < 4; j++) {
                int c0 = wx * 32 + j * 8 + grp;
                bh[j][0] = Bs_hi[c0][kb + tig];
                bh[j][1] = Bs_hi[c0][kb + tig + 4];
                bl[j][0] = Bs_lo[c0][kb + tig];
                bl[j][1] = Bs_lo[c0][kb + tig + 4];
            }
            // Stream A fragments per row-block (8 regs live)
#pragma unroll
            for (int i = 0; i < 4; i++) {
                int r0 = wy * 64 + i * 16 + grp;
                uint32_t ah[4], al[4];
                ah[0] = As_hi[r0][kb + tig];
                ah[1] = As_hi[r0 + 8][kb + tig];
                ah[2] = As_hi[r0][kb + tig + 4];
                ah[3] = As_hi[r0 + 8][kb + tig + 4];
                al[0] = As_lo[r0][kb + tig];
                al[1] = As_lo[r0 + 8][kb + tig];
                al[2] = As_lo[r0][kb + tig + 4];
                al[3] = As_lo[r0 + 8][kb + tig + 4];
#pragma unroll
                for (int j = 0; j < 4; j++) {
                    mma_bf16(acc[i][j], ah, bh[j]);
                    mma_bf16(acc[i][j], al, bh[j]);
                    mma_bf16(acc[i][j], ah, bl[j]);
                }
            }
        }
        __syncthreads();
    }

    // Epilogue
#pragma unroll
    for (int i = 0; i < 4; i++) {
#pragma unroll
        for (int j = 0; j < 4; j++) {
#pragma unroll
            for (int r = 0; r < 4; r++) {
                int m = m0 + wy * 64 + i * 16 + grp + ((r & 2) ? 8 : 0);
                int n = n0 + wx * 32 + j * 8 + 2 * tig + (r & 1);
                float v = acc[i][j][r];
                if constexpr (EPI <= 2) {
                    v += bias[n];
                    int bb = m >> 10, t = m & 1023;
                    int h = n >> 6, d = n & 63;
                    if constexpr (EPI == 1) v += rel[((size_t)h * MAXLEN + t) * D_ + d];
                    float* dst = (EPI == 0) ? g_q : (EPI == 1) ? g_k : g_v;
                    dst[((size_t)(bb * H_ + h) * T_ + t) * D_ + d] = v;
                } else if constexpr (EPI == 3) {
                    if (mask[(z >> 4) * S_ + n]) v = neg_inf();
                    g_s[((size_t)z * T_ + m) * S_ + n] = v;
                } else {
                    out[(size_t)m * E_ + n] = v + bias[n];
                }
            }
        }
    }
}

// ---------------------------------------------------------------------------
// Row softmax over S=1024. One block (256 thr) per row of g_s.
// ---------------------------------------------------------------------------
__global__ __launch_bounds__(256) void softmax_k()
{
    const size_t row = blockIdx.x;
    float* p = g_s + row * S_;
    const int tid = threadIdx.x;

    float4 v = reinterpret_cast<float4*>(p)[tid];

    __shared__ float red[8];
    float mx = fmaxf(fmaxf(v.x, v.y), fmaxf(v.z, v.w));
#pragma unroll
    for (int o = 16; o; o >>= 1) mx = fmaxf(mx, __shfl_xor_sync(0xffffffffu, mx, o));
    if ((tid & 31) == 0) red[tid >> 5] = mx;
    __syncthreads();
    float m8 = red[0];
#pragma unroll
    for (int i = 1; i < 8; i++) m8 = fmaxf(m8, red[i]);
    __syncthreads();

    v.x = __expf(v.x - m8);
    v.y = __expf(v.y - m8);
    v.z = __expf(v.z - m8);
    v.w = __expf(v.w - m8);
    float sm = v.x + v.y + v.z + v.w;
#pragma unroll
    for (int o = 16; o; o >>= 1) sm += __shfl_xor_sync(0xffffffffu, sm, o);
    if ((tid & 31) == 0) red[tid >> 5] = sm;
    __syncthreads();
    float s8 = red[0];
#pragma unroll
    for (int i = 1; i < 8; i++) s8 += red[i];
    float inv = __frcp_rn(s8);

    v.x *= inv; v.y *= inv; v.z *= inv; v.w *= inv;
    reinterpret_cast<float4*>(p)[tid] = v;
}

// ---------------------------------------------------------------------------
// PV (NN): g_ao[b*T+t][h*64+d] = g_s[z] (T x S) @ g_v[z] (S x 64), bf16x3.
// 128x64 tile, BK=32. Warps 4x2: each warp 32 rows x 32 cols.
// ---------------------------------------------------------------------------
__global__ __launch_bounds__(256, 2) void pv_b3()
{
    __shared__ uint32_t As_hi[128][PP], As_lo[128][PP];
    __shared__ uint32_t Bs_hi[64][PP],  Bs_lo[64][PP];

    const int tid = threadIdx.x;
    const int m0 = blockIdx.y * 128;
    const int z  = blockIdx.z;
    const float* Az = g_s + (size_t)z * T_ * S_;
    const float* Vz = g_v + (size_t)z * S_ * D_;

    const int lane = tid & 31, warp = tid >> 5;
    const int wy = warp >> 1, wx = warp & 1;      // 4x2 warp grid: 32x32 per warp
    const int grp = lane >> 2, tig = lane & 3;

    float acc[2][4][4];
#pragma unroll
    for (int i = 0; i < 2; i++)
#pragma unroll
        for (int j = 0; j < 4; j++)
#pragma unroll
            for (int r = 0; r < 4; r++) acc[i][j][r] = 0.0f;

    for (int k0 = 0; k0 < S_; k0 += BK) {
        // A: 128x32 probs -> split pairs
#pragma unroll
        for (int l = 0; l < 4; l++) {
            int idx = tid + l * 256;
            int row = idx >> 3, c4 = idx & 7;
            float4 va = *reinterpret_cast<const float4*>(&Az[(size_t)(m0 + row) * S_ + k0 + c4 * 4]);
            uint32_t h0, l0, h1, l1;
            split2(va.x, va.y, h0, l0);
            split2(va.z, va.w, h1, l1);
            As_hi[row][c4 * 2] = h0; As_hi[row][c4 * 2 + 1] = h1;
            As_lo[row][c4 * 2] = l0; As_lo[row][c4 * 2 + 1] = l1;
        }
        // B: V[k0..k0+32][0..64] transposed into Bs[n][k_pair].
        {
            int p  = tid >> 4;
            int n4 = tid & 15;
            float4 v0 = *reinterpret_cast<const float4*>(&Vz[(size_t)(k0 + 2 * p) * D_ + n4 * 4]);
            float4 v1 = *reinterpret_cast<const float4*>(&Vz[(size_t)(k0 + 2 * p + 1) * D_ + n4 * 4]);
            const float e0[4] = { v0.x, v0.y, v0.z, v0.w };
            const float e1[4] = { v1.x, v1.y, v1.z, v1.w };
#pragma unroll
            for (int e = 0; e < 4; e++) {
                uint32_t h, lo;
                split2(e0[e], e1[e], h, lo);       // (k even, k odd) pair
                Bs_hi[n4 * 4 + e][p] = h;
                Bs_lo[n4 * 4 + e][p] = lo;
            }
        }
        __syncthreads();

#pragma unroll
        for (int ks = 0; ks < 2; ks++) {
            const int kb = ks * 8;
            uint32_t bh[4][2], bl[4][2];
#pragma unroll
            for (int j = 0; j < 4; j++) {
                int c0 = wx * 32 + j * 8 + grp;
                bh[j][0] = Bs_hi[c0][kb + tig];
                bh[j][1] = Bs_hi[c0][kb + tig + 4];
                bl[j][0] = Bs_lo[c0][kb + tig];
                bl[j][1] = Bs_lo[c0][kb + tig + 4];
            }
#pragma unroll
            for (int i = 0; i < 2; i++) {
                int r0 = wy * 32 + i * 16 + grp;
                uint32_t ah[4], al[4];
                ah[0] = As_hi[r0][kb + tig];
                ah[1] = As_hi[r0 + 8][kb + tig];
                ah[2] = As_hi[r0][kb + tig + 4];
                ah[3] = As_hi[r0 + 8][kb + tig + 4];
                al[0] = As_lo[r0][kb + tig];
                al[1] = As_lo[r0 + 8][kb + tig];
                al[2] = As_lo[r0][kb + tig + 4];
                al[3] = As_lo[r0 + 8][kb + tig + 4];
#pragma unroll
                for (int j = 0; j < 4; j++) {
                    mma_bf16(acc[i][j], ah, bh[j]);
                    mma_bf16(acc[i][j], al, bh[j]);
                    mma_bf16(acc[i][j], ah, bl[j]);
                }
            }
        }
        __syncthreads();
    }

    const int bb = z >> 4, h = z & 15;
#pragma unroll
    for (int i = 0; i < 2; i++)
#pragma unroll
        for (int j = 0; j < 4; j++)
#pragma unroll
            for (int r = 0; r < 4; r++) {
                int t = m0 + wy * 32 + i * 16 + grp + ((r & 2) ? 8 : 0);
                int d = wx * 32 + j * 8 + 2 * tig + (r & 1);
                g_ao[((size_t)(bb * T_ + t)) * E_ + h * D_ + d] = acc[i][j][r];
            }
}

extern "C" void kernel_launch(void* const* d_in, const int* in_sizes, int n_in,
                              void* d_out, int out_size)
{
    const float* query = (const float*)d_in[0];
    const float* key   = (const float*)d_in[1];
    const float* value = (const float*)d_in[2];
    const unsigned char* mask = (const unsigned char*)d_in[3];
    const float* q_w = (const float*)d_in[4];
    const float* q_b = (const float*)d_in[5];
    const float* k_w = (const float*)d_in[6];
    const float* k_b = (const float*)d_in[7];
    const float* v_w = (const float*)d_in[8];
    const float* v_b = (const float*)d_in[9];
    const float* o_w = (const float*)d_in[10];
    const float* o_b = (const float*)d_in[11];
    const float* rel = (const float*)d_in[12];
    float* out = (float*)d_out;

    dim3 pg(E_ / 128, (B_ * T_) / 128, 1);
    gemm_b3<0><<<pg, 256>>>(query, q_w, q_b, nullptr, nullptr, nullptr, E_);
    gemm_b3<1><<<pg, 256>>>(key,   k_w, k_b, rel,     nullptr, nullptr, E_);
    gemm_b3<2><<<pg, 256>>>(value, v_w, v_b, nullptr, nullptr, nullptr, E_);

    dim3 sg(S_ / 128, T_ / 128, B_ * H_);
    gemm_b3<3><<<sg, 256>>>(nullptr, nullptr, nullptr, nullptr, mask, nullptr, D_);

    softmax_k<<<B_ * H_ * T_, 256>>>();

    dim3 vg(1, T_ / 128, B_ * H_);
    pv_b3<<<vg, 256>>>();

    dim3 og(E_ / 128, (B_ * T_) / 128, 1);
    gemm_b3<4><<<og, 256>>>(nullptr, o_w, o_b, nullptr, nullptr, out, E_);
}

// round 7
// speedup vs baseline: 2.6857x; 1.3181x over previous
#include <cuda_runtime.h>
#include <cuda_bf16.h>
#include <math.h>
#include <stdint.h>

#define B_ 4
#define T_ 1024
#define S_ 1024
#define E_ 1024
#define H_ 16
#define D_ 64
#define MAXLEN 2048

// Scratch (device globals; referenced ONLY from device code)
__device__ float g_q[B_ * H_ * T_ * D_];          // [z][t][d], z = b*16+h
__device__ float g_k[B_ * H_ * S_ * D_];          // k_proj + rel folded in
__device__ float g_v[B_ * H_ * S_ * D_];
__device__ float g_ao[B_ * T_ * E_];              // attention out, [B*T, E]

#define BK 32      // k per smem tile (fp32 elements) = 16 bf16-pairs
#define PP 20      // smem row stride in pair-words (16 + 4 pad, conflict-free)

__device__ __forceinline__ float neg_big() { return -1e30f; }

// Split two fp32 into packed bf16 hi/lo pair-words (low half = first element).
__device__ __forceinline__ void split2(float x, float y, uint32_t& hi, uint32_t& lo) {
    __nv_bfloat16 xh = __float2bfloat16(x);
    __nv_bfloat16 yh = __float2bfloat16(y);
    __nv_bfloat16 xl = __float2bfloat16(x - __bfloat162float(xh));
    __nv_bfloat16 yl = __float2bfloat16(y - __bfloat162float(yh));
    hi = (uint32_t)__bfloat16_as_ushort(xh) | ((uint32_t)__bfloat16_as_ushort(yh) << 16);
    lo = (uint32_t)__bfloat16_as_ushort(xl) | ((uint32_t)__bfloat16_as_ushort(yl) << 16);
}

__device__ __forceinline__ void mma_bf16(float c[4], const uint32_t a[4], const uint32_t b[2]) {
    asm volatile(
        "mma.sync.aligned.m16n8k16.row.col.f32.bf16.bf16.f32 "
        "{%0,%1,%2,%3}, {%4,%5,%6,%7}, {%8,%9}, {%0,%1,%2,%3};"
        : "+f"(c[0]), "+f"(c[1]), "+f"(c[2]), "+f"(c[3])
        : "r"(a[0]), "r"(a[1]), "r"(a[2]), "r"(a[3]), "r"(b[0]), "r"(b[1]));
}

__device__ __forceinline__ void ldmat_x2_trans(uint32_t& r0, uint32_t& r1, uint32_t addr) {
    asm volatile("ldmatrix.sync.aligned.m8n8.x2.trans.shared.b16 {%0,%1}, [%2];"
                 : "=r"(r0), "=r"(r1) : "r"(addr));
}

// ---------------------------------------------------------------------------
// 128x128 NT GEMM, bf16x3 split: C = A[M,K] @ B[N,K]^T (fp32-accurate).
// EPI 0/1/2: Q/K/V projection -> g_q/g_k/g_v scatter (+bias, +rel for K)
// EPI 4: O proj: g_ao @ W^T + bias -> out
// ---------------------------------------------------------------------------
template <int EPI>
__global__ __launch_bounds__(256, 2) void gemm_b3(
    const float* __restrict__ A_in, const float* __restrict__ Bw,
    const float* __restrict__ bias, const float* __restrict__ rel,
    float* __restrict__ out, int K)
{
    __shared__ uint32_t As_hi[128][PP], As_lo[128][PP];
    __shared__ uint32_t Bs_hi[128][PP], Bs_lo[128][PP];

    const int tid = threadIdx.x;
    const int m0 = blockIdx.y * 128;
    const int n0 = blockIdx.x * 128;

    const float* A = (EPI == 4) ? g_ao : A_in;

    const int lane = tid & 31, warp = tid >> 5;
    const int wy = warp >> 2, wx = warp & 3;      // 2x4 warp grid: 64x32 per warp
    const int grp = lane >> 2, tig = lane & 3;

    float acc[4][4][4];
#pragma unroll
    for (int i = 0; i < 4; i++)
#pragma unroll
        for (int j = 0; j < 4; j++)
#pragma unroll
            for (int r = 0; r < 4; r++) acc[i][j][r] = 0.0f;

    for (int k0 = 0; k0 < K; k0 += BK) {
#pragma unroll
        for (int l = 0; l < 4; l++) {
            int idx = tid + l * 256;
            int row = idx >> 3, c4 = idx & 7;
            float4 va = *reinterpret_cast<const float4*>(&A[(size_t)(m0 + row) * K + k0 + c4 * 4]);
            uint32_t h0, l0, h1, l1;
            split2(va.x, va.y, h0, l0);
            split2(va.z, va.w, h1, l1);
            As_hi[row][c4 * 2] = h0; As_hi[row][c4 * 2 + 1] = h1;
            As_lo[row][c4 * 2] = l0; As_lo[row][c4 * 2 + 1] = l1;
            float4 vb = *reinterpret_cast<const float4*>(&Bw[(size_t)(n0 + row) * K + k0 + c4 * 4]);
            split2(vb.x, vb.y, h0, l0);
            split2(vb.z, vb.w, h1, l1);
            Bs_hi[row][c4 * 2] = h0; Bs_hi[row][c4 * 2 + 1] = h1;
            Bs_lo[row][c4 * 2] = l0; Bs_lo[row][c4 * 2 + 1] = l1;
        }
        __syncthreads();

#pragma unroll
        for (int ks = 0; ks < 2; ks++) {
            const int kb = ks * 8;
            uint32_t bh[4][2], bl[4][2];
#pragma unroll
            for (int j = 0; j < 4; j++) {
                int c0 = wx * 32 + j * 8 + grp;
                bh[j][0] = Bs_hi[c0][kb + tig];
                bh[j][1] = Bs_hi[c0][kb + tig + 4];
                bl[j][0] = Bs_lo[c0][kb + tig];
                bl[j][1] = Bs_lo[c0][kb + tig + 4];
            }
#pragma unroll
            for (int i = 0; i < 4; i++) {
                int r0 = wy * 64 + i * 16 + grp;
                uint32_t ah[4], al[4];
                ah[0] = As_hi[r0][kb + tig];
                ah[1] = As_hi[r0 + 8][kb + tig];
                ah[2] = As_hi[r0][kb + tig + 4];
                ah[3] = As_hi[r0 + 8][kb + tig + 4];
                al[0] = As_lo[r0][kb + tig];
                al[1] = As_lo[r0 + 8][kb + tig];
                al[2] = As_lo[r0][kb + tig + 4];
                al[3] = As_lo[r0 + 8][kb + tig + 4];
#pragma unroll
                for (int j = 0; j < 4; j++) {
                    mma_bf16(acc[i][j], ah, bh[j]);
                    mma_bf16(acc[i][j], al, bh[j]);
                    mma_bf16(acc[i][j], ah, bl[j]);
                }
            }
        }
        __syncthreads();
    }

#pragma unroll
    for (int i = 0; i < 4; i++) {
#pragma unroll
        for (int j = 0; j < 4; j++) {
#pragma unroll
            for (int r = 0; r < 4; r++) {
                int m = m0 + wy * 64 + i * 16 + grp + ((r & 2) ? 8 : 0);
                int n = n0 + wx * 32 + j * 8 + 2 * tig + (r & 1);
                float v = acc[i][j][r];
                if constexpr (EPI <= 2) {
                    v += bias[n];
                    int bb = m >> 10, t = m & 1023;
                    int h = n >> 6, d = n & 63;
                    if constexpr (EPI == 1) v += rel[((size_t)h * MAXLEN + t) * D_ + d];
                    float* dst = (EPI == 0) ? g_q : (EPI == 1) ? g_k : g_v;
                    dst[((size_t)(bb * H_ + h) * T_ + t) * D_ + d] = v;
                } else {
                    out[(size_t)m * E_ + n] = v + bias[n];
                }
            }
        }
    }
}

// ---------------------------------------------------------------------------
// Fused flash attention: per block, 128 q rows of one z = b*16+h head.
// scores (bf16x3) + mask + online softmax + PV (bf16x3) -> g_ao.
// Dynamic smem (u32 words):
//   Qhi[128][36] @0, Qlo @4608, Khi[64][36] @9216, Klo @11520,
//   Vhi[64][36] @13824, Vlo @16128  (V stored s-major bf16 pairs; ldmatrix.trans)
// ---------------------------------------------------------------------------
__global__ __launch_bounds__(256, 2) void flash_attn(const unsigned char* __restrict__ mask)
{
    extern __shared__ uint32_t sm[];
    uint32_t* Qhi = sm;
    uint32_t* Qlo = sm + 4608;
    uint32_t* Khi = sm + 9216;
    uint32_t* Klo = sm + 11520;
    uint32_t* Vhi = sm + 13824;
    uint32_t* Vlo = sm + 16128;

    const int tid = threadIdx.x;
    const int lane = tid & 31, warp = tid >> 5;
    const int grp = lane >> 2, tig = lane & 3;
    const int m0 = blockIdx.x * 128;
    const int z  = blockIdx.y;
    const int bb = z >> 4, h = z & 15;

    const float* Qg = g_q + ((size_t)z * T_ + m0) * D_;
    const float* Kg = g_k + (size_t)z * S_ * D_;
    const float* Vg = g_v + (size_t)z * S_ * D_;
    const unsigned char* mrow_g = mask + (size_t)bb * S_;

    uint32_t sbase;
    asm("{.reg .u64 t; cvta.to.shared.u64 t, %1; cvt.u32.u64 %0, t;}"
        : "=r"(sbase) : "l"(sm));
    const uint32_t vrow_h = sbase + 13824 * 4 + (lane & 15) * 144;  // +ks*2304 +jd*16

    // Load + split Q block (128 x 64): 2048 float4, 8 per thread
#pragma unroll
    for (int l = 0; l < 8; l++) {
        int idx = tid + l * 256;
        int row = idx >> 4, c4 = idx & 15;
        float4 va = *reinterpret_cast<const float4*>(&Qg[(size_t)row * D_ + c4 * 4]);
        uint32_t h0, l0, h1, l1;
        split2(va.x, va.y, h0, l0);
        split2(va.z, va.w, h1, l1);
        Qhi[row * 36 + c4 * 2] = h0; Qhi[row * 36 + c4 * 2 + 1] = h1;
        Qlo[row * 36 + c4 * 2] = l0; Qlo[row * 36 + c4 * 2 + 1] = l1;
    }

    float accO[8][4];
#pragma unroll
    for (int jd = 0; jd < 8; jd++)
#pragma unroll
        for (int r = 0; r < 4; r++) accO[jd][r] = 0.0f;
    float m0r = -1e29f, m1r = -1e29f, l0r = 0.0f, l1r = 0.0f;

    const int r0 = warp * 16 + grp;

    for (int s0 = 0; s0 < S_; s0 += 64) {
        // Fill K and V tiles (64 x 64 each): 1024 tasks, 4 per thread
#pragma unroll
        for (int l = 0; l < 4; l++) {
            int idx = tid + l * 256;
            int row = idx >> 4, c4 = idx & 15;
            float4 vk = *reinterpret_cast<const float4*>(&Kg[(size_t)(s0 + row) * D_ + c4 * 4]);
            uint32_t h0, l0w, h1, l1w;
            split2(vk.x, vk.y, h0, l0w);
            split2(vk.z, vk.w, h1, l1w);
            Khi[row * 36 + c4 * 2] = h0; Khi[row * 36 + c4 * 2 + 1] = h1;
            Klo[row * 36 + c4 * 2] = l0w; Klo[row * 36 + c4 * 2 + 1] = l1w;
            float4 vv = *reinterpret_cast<const float4*>(&Vg[(size_t)(s0 + row) * D_ + c4 * 4]);
            split2(vv.x, vv.y, h0, l0w);
            split2(vv.z, vv.w, h1, l1w);
            Vhi[row * 36 + c4 * 2] = h0; Vhi[row * 36 + c4 * 2 + 1] = h1;
            Vlo[row * 36 + c4 * 2] = l0w; Vlo[row * 36 + c4 * 2 + 1] = l1w;
        }
        __syncthreads();

        // Scores: warp's 16 rows x 64 cols, bf16x3
        float acc[8][4];
#pragma unroll
        for (int j = 0; j < 8; j++)
#pragma unroll
            for (int r = 0; r < 4; r++) acc[j][r] = 0.0f;

#pragma unroll
        for (int ks = 0; ks < 4; ks++) {
            const int kb = ks * 8;
            uint32_t qh[4], ql[4];
            qh[0] = Qhi[r0 * 36 + kb + tig];
            qh[1] = Qhi[(r0 + 8) * 36 + kb + tig];
            qh[2] = Qhi[r0 * 36 + kb + tig + 4];
            qh[3] = Qhi[(r0 + 8) * 36 + kb + tig + 4];
            ql[0] = Qlo[r0 * 36 + kb + tig];
            ql[1] = Qlo[(r0 + 8) * 36 + kb + tig];
            ql[2] = Qlo[r0 * 36 + kb + tig + 4];
            ql[3] = Qlo[(r0 + 8) * 36 + kb + tig + 4];
#pragma unroll
            for (int j = 0; j < 8; j++) {
                int c0 = j * 8 + grp;
                uint32_t kh[2], kl[2];
                kh[0] = Khi[c0 * 36 + kb + tig];
                kh[1] = Khi[c0 * 36 + kb + tig + 4];
                kl[0] = Klo[c0 * 36 + kb + tig];
                kl[1] = Klo[c0 * 36 + kb + tig + 4];
                mma_bf16(acc[j], qh, kh);
                mma_bf16(acc[j], ql, kh);
                mma_bf16(acc[j], qh, kl);
            }
        }

        // Mask
#pragma unroll
        for (int j = 0; j < 8; j++) {
            int c = s0 + j * 8 + 2 * tig;
            if (mrow_g[c])     { acc[j][0] = neg_big(); acc[j][2] = neg_big(); }
            if (mrow_g[c + 1]) { acc[j][1] = neg_big(); acc[j][3] = neg_big(); }
        }

        // Row max (rows grp and grp+8)
        float tm0 = neg_big(), tm1 = neg_big();
#pragma unroll
        for (int j = 0; j < 8; j++) {
            tm0 = fmaxf(tm0, fmaxf(acc[j][0], acc[j][1]));
            tm1 = fmaxf(tm1, fmaxf(acc[j][2], acc[j][3]));
        }
        tm0 = fmaxf(tm0, __shfl_xor_sync(0xffffffffu, tm0, 1));
        tm0 = fmaxf(tm0, __shfl_xor_sync(0xffffffffu, tm0, 2));
        tm1 = fmaxf(tm1, __shfl_xor_sync(0xffffffffu, tm1, 1));
        tm1 = fmaxf(tm1, __shfl_xor_sync(0xffffffffu, tm1, 2));

        float mn0 = fmaxf(fmaxf(m0r, tm0), -1e29f);
        float mn1 = fmaxf(fmaxf(m1r, tm1), -1e29f);
        float sc0 = __expf(m0r - mn0);
        float sc1 = __expf(m1r - mn1);

        // exp + row sum
        float ts0 = 0.0f, ts1 = 0.0f;
#pragma unroll
        for (int j = 0; j < 8; j++) {
            acc[j][0] = __expf(acc[j][0] - mn0);
            acc[j][1] = __expf(acc[j][1] - mn0);
            acc[j][2] = __expf(acc[j][2] - mn1);
            acc[j][3] = __expf(acc[j][3] - mn1);
            ts0 += acc[j][0] + acc[j][1];
            ts1 += acc[j][2] + acc[j][3];
        }
        ts0 += __shfl_xor_sync(0xffffffffu, ts0, 1);
        ts0 += __shfl_xor_sync(0xffffffffu, ts0, 2);
        ts1 += __shfl_xor_sync(0xffffffffu, ts1, 1);
        ts1 += __shfl_xor_sync(0xffffffffu, ts1, 2);

        l0r = l0r * sc0 + ts0;
        l1r = l1r * sc1 + ts1;
        m0r = mn0; m1r = mn1;

        // Rescale O accumulator
#pragma unroll
        for (int jd = 0; jd < 8; jd++) {
            accO[jd][0] *= sc0; accO[jd][1] *= sc0;
            accO[jd][2] *= sc1; accO[jd][3] *= sc1;
        }

        // PV: probs (register A fragments) @ V tile (ldmatrix.trans B fragments)
#pragma unroll
        for (int ks = 0; ks < 4; ks++) {
            uint32_t ah[4], al[4];
            split2(acc[2 * ks][0],     acc[2 * ks][1],     ah[0], al[0]);
            split2(acc[2 * ks][2],     acc[2 * ks][3],     ah[1], al[1]);
            split2(acc[2 * ks + 1][0], acc[2 * ks + 1][1], ah[2], al[2]);
            split2(acc[2 * ks + 1][2], acc[2 * ks + 1][3], ah[3], al[3]);
            uint32_t rbase = vrow_h + ks * 2304;
#pragma unroll
            for (int jd = 0; jd < 8; jd++) {
                uint32_t bh[2], bl[2];
                ldmat_x2_trans(bh[0], bh[1], rbase + jd * 16);
                ldmat_x2_trans(bl[0], bl[1], rbase + jd * 16 + 9216);
                mma_bf16(accO[jd], ah, bh);
                mma_bf16(accO[jd], al, bh);
                mma_bf16(accO[jd], ah, bl);
            }
        }
        __syncthreads();
    }

    // Epilogue: O / l -> g_ao
    float inv0 = 1.0f / l0r, inv1 = 1.0f / l1r;
    size_t base0 = ((size_t)(bb * T_) + m0 + warp * 16 + grp) * E_ + h * 64;
    size_t base1 = base0 + (size_t)8 * E_;
#pragma unroll
    for (int jd = 0; jd < 8; jd++) {
        int d = jd * 8 + 2 * tig;
        g_ao[base0 + d]     = accO[jd][0] * inv0;
        g_ao[base0 + d + 1] = accO[jd][1] * inv0;
        g_ao[base1 + d]     = accO[jd][2] * inv1;
        g_ao[base1 + d + 1] = accO[jd][3] * inv1;
    }
}

extern "C" void kernel_launch(void* const* d_in, const int* in_sizes, int n_in,
                              void* d_out, int out_size)
{
    const float* query = (const float*)d_in[0];
    const float* key   = (const float*)d_in[1];
    const float* value = (const float*)d_in[2];
    const unsigned char* mask = (const unsigned char*)d_in[3];
    const float* q_w = (const float*)d_in[4];
    const float* q_b = (const float*)d_in[5];
    const float* k_w = (const float*)d_in[6];
    const float* k_b = (const float*)d_in[7];
    const float* v_w = (const float*)d_in[8];
    const float* v_b = (const float*)d_in[9];
    const float* o_w = (const float*)d_in[10];
    const float* o_b = (const float*)d_in[11];
    const float* rel = (const float*)d_in[12];
    float* out = (float*)d_out;

    cudaFuncSetAttribute(flash_attn, cudaFuncAttributeMaxDynamicSharedMemorySize, 73728);

    dim3 pg(E_ / 128, (B_ * T_) / 128, 1);
    gemm_b3<0><<<pg, 256>>>(query, q_w, q_b, nullptr, nullptr, E_);
    gemm_b3<1><<<pg, 256>>>(key,   k_w, k_b, rel,     nullptr, E_);
    gemm_b3<2><<<pg, 256>>>(value, v_w, v_b, nullptr, nullptr, E_);

    dim3 fg(T_ / 128, B_ * H_, 1);
    flash_attn<<<fg, 256, 73728>>>(mask);

    dim3 og(E_ / 128, (B_ * T_) / 128, 1);
    gemm_b3<4><<<og, 256>>>(nullptr, o_w, o_b, nullptr, out, E_);
}

// round 8
// speedup vs baseline: 2.7272x; 1.0155x over previous
#include <cuda_runtime.h>
#include <cuda_bf16.h>
#include <math.h>
#include <stdint.h>

#define B_ 4
#define T_ 1024
#define S_ 1024
#define E_ 1024
#define H_ 16
#define D_ 64
#define MAXLEN 2048

// Scratch (device globals; referenced ONLY from device code)
__device__ float g_q[B_ * H_ * T_ * D_];          // [z][t][d], z = b*16+h
__device__ float g_k[B_ * H_ * S_ * D_];          // k_proj + rel folded in
__device__ float g_v[B_ * H_ * S_ * D_];
__device__ float g_ao[B_ * T_ * E_];              // attention out, [B*T, E]

__device__ __forceinline__ float neg_big() { return -1e30f; }

// Split two fp32 into packed bf16 hi/lo pair-words (low half = first element).
__device__ __forceinline__ void split2(float x, float y, uint32_t& hi, uint32_t& lo) {
    __nv_bfloat16 xh = __float2bfloat16(x);
    __nv_bfloat16 yh = __float2bfloat16(y);
    __nv_bfloat16 xl = __float2bfloat16(x - __bfloat162float(xh));
    __nv_bfloat16 yl = __float2bfloat16(y - __bfloat162float(yh));
    hi = (uint32_t)__bfloat16_as_ushort(xh) | ((uint32_t)__bfloat16_as_ushort(yh) << 16);
    lo = (uint32_t)__bfloat16_as_ushort(xl) | ((uint32_t)__bfloat16_as_ushort(yl) << 16);
}

__device__ __forceinline__ void mma_bf16(float c[4], const uint32_t a[4], const uint32_t b[2]) {
    asm volatile(
        "mma.sync.aligned.m16n8k16.row.col.f32.bf16.bf16.f32 "
        "{%0,%1,%2,%3}, {%4,%5,%6,%7}, {%8,%9}, {%0,%1,%2,%3};"
        : "+f"(c[0]), "+f"(c[1]), "+f"(c[2]), "+f"(c[3])
        : "r"(a[0]), "r"(a[1]), "r"(a[2]), "r"(a[3]), "r"(b[0]), "r"(b[1]));
}

__device__ __forceinline__ void ldmat_x2_trans(uint32_t& r0, uint32_t& r1, uint32_t addr) {
    asm volatile("ldmatrix.sync.aligned.m8n8.x2.trans.shared.b16 {%0,%1}, [%2];"
                 : "=r"(r0), "=r"(r1) : "r"(addr));
}

__device__ __forceinline__ void cpa16(uint32_t dst, const void* src) {
    asm volatile("cp.async.cg.shared.global [%0], [%1], 16;" :: "r"(dst), "l"(src));
}
template <int N>
__device__ __forceinline__ void cpa_wait() {
    asm volatile("cp.async.wait_group %0;" :: "n"(N) : "memory");
}

// ---------------------------------------------------------------------------
// 128x128 NT GEMM, bf16x3 split, cp.async double-buffered staging.
// EPI 0/1/2: Q/K/V projection -> g_q/g_k/g_v scatter (+bias, +rel for K)
// EPI 4: O proj: g_ao @ W^T + bias -> out
// Dynamic smem (bytes):
//   Araw[2][128*32]f @0, Braw[2][128*32]f @32768,
//   Ahi @65536, Alo @75776, Bhi @86016, Blo @96256   (u32[128*20] each)
// total 106496 B
// ---------------------------------------------------------------------------
template <int EPI>
__global__ __launch_bounds__(256, 2) void gemm_b3(
    const float* __restrict__ A_in, const float* __restrict__ Bw,
    const float* __restrict__ bias, const float* __restrict__ rel,
    float* __restrict__ out, int K)
{
    extern __shared__ float dsm[];
    float* Araw = dsm;                                   // [2][4096]
    float* Braw = dsm + 8192;                            // [2][4096]
    uint32_t* Ahi = reinterpret_cast<uint32_t*>(dsm) + 16384;
    uint32_t* Alo = Ahi + 2560;
    uint32_t* Bhi = Ahi + 5120;
    uint32_t* Blo = Ahi + 7680;

    const int tid = threadIdx.x;
    const int m0 = blockIdx.y * 128;
    const int n0 = blockIdx.x * 128;

    const float* A = (EPI == 4) ? g_ao : A_in;

    uint32_t sbase;
    asm("{.reg .u64 t; cvta.to.shared.u64 t, %1; cvt.u32.u64 %0, t;}"
        : "=r"(sbase) : "l"(dsm));

    const int lane = tid & 31, warp = tid >> 5;
    const int wy = warp >> 2, wx = warp & 3;      // 2x4 warp grid: 64x32 per warp
    const int grp = lane >> 2, tig = lane & 3;

    const int frow = tid >> 3, fc4 = tid & 3;     // fill/convert mapping helpers

    float acc[4][4][4];
#pragma unroll
    for (int i = 0; i < 4; i++)
#pragma unroll
        for (int j = 0; j < 4; j++)
#pragma unroll
            for (int r = 0; r < 4; r++) acc[i][j][r] = 0.0f;

    const int nT = K / 32;

    // Prologue: fill stage 0 for tile 0
    {
#pragma unroll
        for (int l = 0; l < 4; l++) {
            int idx = tid + l * 256;
            int row = idx >> 3, c4 = idx & 7;
            uint32_t off = (uint32_t)(row * 32 + c4 * 4) * 4;
            cpa16(sbase + off, &A[(size_t)(m0 + row) * K + c4 * 4]);
            cpa16(sbase + 32768 + off, &Bw[(size_t)(n0 + row) * K + c4 * 4]);
        }
        asm volatile("cp.async.commit_group;" ::: "memory");
    }

    for (int t = 0; t < nT; t++) {
        const int k0 = t * 32;
        const int st = t & 1;

        if (t + 1 < nT) {
            const int sn = (t + 1) & 1;
            const int kn = k0 + 32;
#pragma unroll
            for (int l = 0; l < 4; l++) {
                int idx = tid + l * 256;
                int row = idx >> 3, c4 = idx & 7;
                uint32_t off = (uint32_t)(sn * 4096 + row * 32 + c4 * 4) * 4;
                cpa16(sbase + off, &A[(size_t)(m0 + row) * K + kn + c4 * 4]);
                cpa16(sbase + 32768 + off, &Bw[(size_t)(n0 + row) * K + kn + c4 * 4]);
            }
            asm volatile("cp.async.commit_group;" ::: "memory");
            cpa_wait<1>();
        } else {
            cpa_wait<0>();
        }
        __syncthreads();

        // Convert: staging fp32 -> bf16 pair buffers
#pragma unroll
        for (int l = 0; l < 4; l++) {
            int idx = tid + l * 256;
            int row = idx >> 3, c4 = idx & 7;
            float4 va = *reinterpret_cast<const float4*>(&Araw[st * 4096 + row * 32 + c4 * 4]);
            uint32_t h0, l0, h1, l1;
            split2(va.x, va.y, h0, l0);
            split2(va.z, va.w, h1, l1);
            Ahi[row * 20 + c4 * 2] = h0; Ahi[row * 20 + c4 * 2 + 1] = h1;
            Alo[row * 20 + c4 * 2] = l0; Alo[row * 20 + c4 * 2 + 1] = l1;
            float4 vb = *reinterpret_cast<const float4*>(&Braw[st * 4096 + row * 32 + c4 * 4]);
            split2(vb.x, vb.y, h0, l0);
            split2(vb.z, vb.w, h1, l1);
            Bhi[row * 20 + c4 * 2] = h0; Bhi[row * 20 + c4 * 2 + 1] = h1;
            Blo[row * 20 + c4 * 2] = l0; Blo[row * 20 + c4 * 2 + 1] = l1;
        }
        __syncthreads();

        // MMA phase
#pragma unroll
        for (int ks = 0; ks < 2; ks++) {
            const int kb = ks * 8;
            uint32_t bh[4][2], bl[4][2];
#pragma unroll
            for (int j = 0; j < 4; j++) {
                int c0 = wx * 32 + j * 8 + grp;
                bh[j][0] = Bhi[c0 * 20 + kb + tig];
                bh[j][1] = Bhi[c0 * 20 + kb + tig + 4];
                bl[j][0] = Blo[c0 * 20 + kb + tig];
                bl[j][1] = Blo[c0 * 20 + kb + tig + 4];
            }
#pragma unroll
            for (int i = 0; i < 4; i++) {
                int r0 = wy * 64 + i * 16 + grp;
                uint32_t ah[4], al[4];
                ah[0] = Ahi[r0 * 20 + kb + tig];
                ah[1] = Ahi[(r0 + 8) * 20 + kb + tig];
                ah[2] = Ahi[r0 * 20 + kb + tig + 4];
                ah[3] = Ahi[(r0 + 8) * 20 + kb + tig + 4];
                al[0] = Alo[r0 * 20 + kb + tig];
                al[1] = Alo[(r0 + 8) * 20 + kb + tig];
                al[2] = Alo[r0 * 20 + kb + tig + 4];
                al[3] = Alo[(r0 + 8) * 20 + kb + tig + 4];
#pragma unroll
                for (int j = 0; j < 4; j++) {
                    mma_bf16(acc[i][j], ah, bh[j]);
                    mma_bf16(acc[i][j], al, bh[j]);
                    mma_bf16(acc[i][j], ah, bl[j]);
                }
            }
        }
        __syncthreads();
    }

#pragma unroll
    for (int i = 0; i < 4; i++) {
#pragma unroll
        for (int j = 0; j < 4; j++) {
#pragma unroll
            for (int r = 0; r < 4; r++) {
                int m = m0 + wy * 64 + i * 16 + grp + ((r & 2) ? 8 : 0);
                int n = n0 + wx * 32 + j * 8 + 2 * tig + (r & 1);
                float v = acc[i][j][r];
                if constexpr (EPI <= 2) {
                    v += bias[n];
                    int bb = m >> 10, tt = m & 1023;
                    int h = n >> 6, d = n & 63;
                    if constexpr (EPI == 1) v += rel[((size_t)h * MAXLEN + tt) * D_ + d];
                    float* dst = (EPI == 0) ? g_q : (EPI == 1) ? g_k : g_v;
                    dst[((size_t)(bb * H_ + h) * T_ + tt) * D_ + d] = v;
                } else {
                    out[(size_t)m * E_ + n] = v + bias[n];
                }
            }
        }
    }
}

// ---------------------------------------------------------------------------
// Fused flash attention (unchanged from R7): 128 q rows per block of head z.
// Dynamic smem (u32 words):
//   Qhi[128][36] @0, Qlo @4608, Khi[64][36] @9216, Klo @11520,
//   Vhi[64][36] @13824, Vlo @16128
// ---------------------------------------------------------------------------
__global__ __launch_bounds__(256, 2) void flash_attn(const unsigned char* __restrict__ mask)
{
    extern __shared__ uint32_t sm[];
    uint32_t* Qhi = sm;
    uint32_t* Qlo = sm + 4608;
    uint32_t* Khi = sm + 9216;
    uint32_t* Klo = sm + 11520;
    uint32_t* Vhi = sm + 13824;
    uint32_t* Vlo = sm + 16128;

    const int tid = threadIdx.x;
    const int lane = tid & 31, warp = tid >> 5;
    const int grp = lane >> 2, tig = lane & 3;
    const int m0 = blockIdx.x * 128;
    const int z  = blockIdx.y;
    const int bb = z >> 4, h = z & 15;

    const float* Qg = g_q + ((size_t)z * T_ + m0) * D_;
    const float* Kg = g_k + (size_t)z * S_ * D_;
    const float* Vg = g_v + (size_t)z * S_ * D_;
    const unsigned char* mrow_g = mask + (size_t)bb * S_;

    uint32_t sbase;
    asm("{.reg .u64 t; cvta.to.shared.u64 t, %1; cvt.u32.u64 %0, t;}"
        : "=r"(sbase) : "l"(sm));
    const uint32_t vrow_h = sbase + 13824 * 4 + (lane & 15) * 144;

#pragma unroll
    for (int l = 0; l < 8; l++) {
        int idx = tid + l * 256;
        int row = idx >> 4, c4 = idx & 15;
        float4 va = *reinterpret_cast<const float4*>(&Qg[(size_t)row * D_ + c4 * 4]);
        uint32_t h0, l0, h1, l1;
        split2(va.x, va.y, h0, l0);
        split2(va.z, va.w, h1, l1);
        Qhi[row * 36 + c4 * 2] = h0; Qhi[row * 36 + c4 * 2 + 1] = h1;
        Qlo[row * 36 + c4 * 2] = l0; Qlo[row * 36 + c4 * 2 + 1] = l1;
    }

    float accO[8][4];
#pragma unroll
    for (int jd = 0; jd < 8; jd++)
#pragma unroll
        for (int r = 0; r < 4; r++) accO[jd][r] = 0.0f;
    float m0r = -1e29f, m1r = -1e29f, l0r = 0.0f, l1r = 0.0f;

    const int r0 = warp * 16 + grp;

    for (int s0 = 0; s0 < S_; s0 += 64) {
#pragma unroll
        for (int l = 0; l < 4; l++) {
            int idx = tid + l * 256;
            int row = idx >> 4, c4 = idx & 15;
            float4 vk = *reinterpret_cast<const float4*>(&Kg[(size_t)(s0 + row) * D_ + c4 * 4]);
            uint32_t h0, l0w, h1, l1w;
            split2(vk.x, vk.y, h0, l0w);
            split2(vk.z, vk.w, h1, l1w);
            Khi[row * 36 + c4 * 2] = h0; Khi[row * 36 + c4 * 2 + 1] = h1;
            Klo[row * 36 + c4 * 2] = l0w; Klo[row * 36 + c4 * 2 + 1] = l1w;
            float4 vv = *reinterpret_cast<const float4*>(&Vg[(size_t)(s0 + row) * D_ + c4 * 4]);
            split2(vv.x, vv.y, h0, l0w);
            split2(vv.z, vv.w, h1, l1w);
            Vhi[row * 36 + c4 * 2] = h0; Vhi[row * 36 + c4 * 2 + 1] = h1;
            Vlo[row * 36 + c4 * 2] = l0w; Vlo[row * 36 + c4 * 2 + 1] = l1w;
        }
        __syncthreads();

        float acc[8][4];
#pragma unroll
        for (int j = 0; j < 8; j++)
#pragma unroll
            for (int r = 0; r < 4; r++) acc[j][r] = 0.0f;

#pragma unroll
        for (int ks = 0; ks < 4; ks++) {
            const int kb = ks * 8;
            uint32_t qh[4], ql[4];
            qh[0] = Qhi[r0 * 36 + kb + tig];
            qh[1] = Qhi[(r0 + 8) * 36 + kb + tig];
            qh[2] = Qhi[r0 * 36 + kb + tig + 4];
            qh[3] = Qhi[(r0 + 8) * 36 + kb + tig + 4];
            ql[0] = Qlo[r0 * 36 + kb + tig];
            ql[1] = Qlo[(r0 + 8) * 36 + kb + tig];
            ql[2] = Qlo[r0 * 36 + kb + tig + 4];
            ql[3] = Qlo[(r0 + 8) * 36 + kb + tig + 4];
#pragma unroll
            for (int j = 0; j < 8; j++) {
                int c0 = j * 8 + grp;
                uint32_t kh[2], kl[2];
                kh[0] = Khi[c0 * 36 + kb + tig];
                kh[1] = Khi[c0 * 36 + kb + tig + 4];
                kl[0] = Klo[c0 * 36 + kb + tig];
                kl[1] = Klo[c0 * 36 + kb + tig + 4];
                mma_bf16(acc[j], qh, kh);
                mma_bf16(acc[j], ql, kh);
                mma_bf16(acc[j], qh, kl);
            }
        }

#pragma unroll
        for (int j = 0; j < 8; j++) {
            int c = s0 + j * 8 + 2 * tig;
            if (mrow_g[c])     { acc[j][0] = neg_big(); acc[j][2] = neg_big(); }
            if (mrow_g[c + 1]) { acc[j][1] = neg_big(); acc[j][3] = neg_big(); }
        }

        float tm0 = neg_big(), tm1 = neg_big();
#pragma unroll
        for (int j = 0; j < 8; j++) {
            tm0 = fmaxf(tm0, fmaxf(acc[j][0], acc[j][1]));
            tm1 = fmaxf(tm1, fmaxf(acc[j][2], acc[j][3]));
        }
        tm0 = fmaxf(tm0, __shfl_xor_sync(0xffffffffu, tm0, 1));
        tm0 = fmaxf(tm0, __shfl_xor_sync(0xffffffffu, tm0, 2));
        tm1 = fmaxf(tm1, __shfl_xor_sync(0xffffffffu, tm1, 1));
        tm1 = fmaxf(tm1, __shfl_xor_sync(0xffffffffu, tm1, 2));

        float mn0 = fmaxf(fmaxf(m0r, tm0), -1e29f);
        float mn1 = fmaxf(fmaxf(m1r, tm1), -1e29f);
        float sc0 = __expf(m0r - mn0);
        float sc1 = __expf(m1r - mn1);

        float ts0 = 0.0f, ts1 = 0.0f;
#pragma unroll
        for (int j = 0; j < 8; j++) {
            acc[j][0] = __expf(acc[j][0] - mn0);
            acc[j][1] = __expf(acc[j][1] - mn0);
            acc[j][2] = __expf(acc[j][2] - mn1);
            acc[j][3] = __expf(acc[j][3] - mn1);
            ts0 += acc[j][0] + acc[j][1];
            ts1 += acc[j][2] + acc[j][3];
        }
        ts0 += __shfl_xor_sync(0xffffffffu, ts0, 1);
        ts0 += __shfl_xor_sync(0xffffffffu, ts0, 2);
        ts1 += __shfl_xor_sync(0xffffffffu, ts1, 1);
        ts1 += __shfl_xor_sync(0xffffffffu, ts1, 2);

        l0r = l0r * sc0 + ts0;
        l1r = l1r * sc1 + ts1;
        m0r = mn0; m1r = mn1;

#pragma unroll
        for (int jd = 0; jd < 8; jd++) {
            accO[jd][0] *= sc0; accO[jd][1] *= sc0;
            accO[jd][2] *= sc1; accO[jd][3] *= sc1;
        }

#pragma unroll
        for (int ks = 0; ks < 4; ks++) {
            uint32_t ah[4], al[4];
            split2(acc[2 * ks][0],     acc[2 * ks][1],     ah[0], al[0]);
            split2(acc[2 * ks][2],     acc[2 * ks][3],     ah[1], al[1]);
            split2(acc[2 * ks + 1][0], acc[2 * ks + 1][1], ah[2], al[2]);
            split2(acc[2 * ks + 1][2], acc[2 * ks + 1][3], ah[3], al[3]);
            uint32_t rbase = vrow_h + ks * 2304;
#pragma unroll
            for (int jd = 0; jd < 8; jd++) {
                uint32_t bh[2], bl[2];
                ldmat_x2_trans(bh[0], bh[1], rbase + jd * 16);
                ldmat_x2_trans(bl[0], bl[1], rbase + jd * 16 + 9216);
                mma_bf16(accO[jd], ah, bh);
                mma_bf16(accO[jd], al, bh);
                mma_bf16(accO[jd], ah, bl);
            }
        }
        __syncthreads();
    }

    float inv0 = 1.0f / l0r, inv1 = 1.0f / l1r;
    size_t base0 = ((size_t)(bb * T_) + m0 + warp * 16 + grp) * E_ + h * 64;
    size_t base1 = base0 + (size_t)8 * E_;
#pragma unroll
    for (int jd = 0; jd < 8; jd++) {
        int d = jd * 8 + 2 * tig;
        g_ao[base0 + d]     = accO[jd][0] * inv0;
        g_ao[base0 + d + 1] = accO[jd][1] * inv0;
        g_ao[base1 + d]     = accO[jd][2] * inv1;
        g_ao[base1 + d + 1] = accO[jd][3] * inv1;
    }
}

extern "C" void kernel_launch(void* const* d_in, const int* in_sizes, int n_in,
                              void* d_out, int out_size)
{
    const float* query = (const float*)d_in[0];
    const float* key   = (const float*)d_in[1];
    const float* value = (const float*)d_in[2];
    const unsigned char* mask = (const unsigned char*)d_in[3];
    const float* q_w = (const float*)d_in[4];
    const float* q_b = (const float*)d_in[5];
    const float* k_w = (const float*)d_in[6];
    const float* k_b = (const float*)d_in[7];
    const float* v_w = (const float*)d_in[8];
    const float* v_b = (const float*)d_in[9];
    const float* o_w = (const float*)d_in[10];
    const float* o_b = (const float*)d_in[11];
    const float* rel = (const float*)d_in[12];
    float* out = (float*)d_out;

    const int GSMEM = 106496;
    cudaFuncSetAttribute(gemm_b3<0>, cudaFuncAttributeMaxDynamicSharedMemorySize, GSMEM);
    cudaFuncSetAttribute(gemm_b3<1>, cudaFuncAttributeMaxDynamicSharedMemorySize, GSMEM);
    cudaFuncSetAttribute(gemm_b3<2>, cudaFuncAttributeMaxDynamicSharedMemorySize, GSMEM);
    cudaFuncSetAttribute(gemm_b3<4>, cudaFuncAttributeMaxDynamicSharedMemorySize, GSMEM);
    cudaFuncSetAttribute(flash_attn, cudaFuncAttributeMaxDynamicSharedMemorySize, 73728);

    dim3 pg(E_ / 128, (B_ * T_) / 128, 1);
    gemm_b3<0><<<pg, 256, GSMEM>>>(query, q_w, q_b, nullptr, nullptr, E_);
    gemm_b3<1><<<pg, 256, GSMEM>>>(key,   k_w, k_b, rel,     nullptr, E_);
    gemm_b3<2><<<pg, 256, GSMEM>>>(value, v_w, v_b, nullptr, nullptr, E_);

    dim3 fg(T_ / 128, B_ * H_, 1);
    flash_attn<<<fg, 256, 73728>>>(mask);

    dim3 og(E_ / 128, (B_ * T_) / 128, 1);
    gemm_b3<4><<<og, 256, GSMEM>>>(nullptr, o_w, o_b, nullptr, out, E_);
}

// round 9
// speedup vs baseline: 2.9474x; 1.0808x over previous
#include <cuda_runtime.h>
#include <cuda_bf16.h>
#include <math.h>
#include <stdint.h>

#define B_ 4
#define T_ 1024
#define S_ 1024
#define E_ 1024
#define H_ 16
#define D_ 64
#define MAXLEN 2048

// ---------------- Pre-split bf16-pair device globals ----------------
// Activations [4096][512] pair-words (pairs along K)
__device__ uint32_t qa_hi[4096 * 512], qa_lo[4096 * 512];
__device__ uint32_t ka_hi[4096 * 512], ka_lo[4096 * 512];
__device__ uint32_t va_hi[4096 * 512], va_lo[4096 * 512];
__device__ uint32_t ao_hi[4096 * 512], ao_lo[4096 * 512];   // attention out (pair)
// Weights [1024][512]
__device__ uint32_t qw_hi[1024 * 512], qw_lo[1024 * 512];
__device__ uint32_t kw_hi[1024 * 512], kw_lo[1024 * 512];
__device__ uint32_t vw_hi[1024 * 512], vw_lo[1024 * 512];
__device__ uint32_t ow_hi[1024 * 512], ow_lo[1024 * 512];
// Projected q/k/v: [z][t][32] pair-words (pairs along d), z = b*16+h
__device__ uint32_t gq_hi[64 * 1024 * 32], gq_lo[64 * 1024 * 32];
__device__ uint32_t gk_hi[64 * 1024 * 32], gk_lo[64 * 1024 * 32];
__device__ uint32_t gv_hi[64 * 1024 * 32], gv_lo[64 * 1024 * 32];

__device__ __forceinline__ float neg_big() { return -1e30f; }

__device__ __forceinline__ void split2(float x, float y, uint32_t& hi, uint32_t& lo) {
    __nv_bfloat16 xh = __float2bfloat16(x);
    __nv_bfloat16 yh = __float2bfloat16(y);
    __nv_bfloat16 xl = __float2bfloat16(x - __bfloat162float(xh));
    __nv_bfloat16 yl = __float2bfloat16(y - __bfloat162float(yh));
    hi = (uint32_t)__bfloat16_as_ushort(xh) | ((uint32_t)__bfloat16_as_ushort(yh) << 16);
    lo = (uint32_t)__bfloat16_as_ushort(xl) | ((uint32_t)__bfloat16_as_ushort(yl) << 16);
}

__device__ __forceinline__ void mma_bf16(float c[4], const uint32_t a[4], const uint32_t b[2]) {
    asm volatile(
        "mma.sync.aligned.m16n8k16.row.col.f32.bf16.bf16.f32 "
        "{%0,%1,%2,%3}, {%4,%5,%6,%7}, {%8,%9}, {%0,%1,%2,%3};"
        : "+f"(c[0]), "+f"(c[1]), "+f"(c[2]), "+f"(c[3])
        : "r"(a[0]), "r"(a[1]), "r"(a[2]), "r"(a[3]), "r"(b[0]), "r"(b[1]));
}

__device__ __forceinline__ void ldmat_x4(uint32_t r[4], uint32_t addr) {
    asm volatile("ldmatrix.sync.aligned.m8n8.x4.shared.b16 {%0,%1,%2,%3}, [%4];"
                 : "=r"(r[0]), "=r"(r[1]), "=r"(r[2]), "=r"(r[3]) : "r"(addr));
}
__device__ __forceinline__ void ldmat_x2(uint32_t& r0, uint32_t& r1, uint32_t addr) {
    asm volatile("ldmatrix.sync.aligned.m8n8.x2.shared.b16 {%0,%1}, [%2];"
                 : "=r"(r0), "=r"(r1) : "r"(addr));
}
__device__ __forceinline__ void ldmat_x2_trans(uint32_t& r0, uint32_t& r1, uint32_t addr) {
    asm volatile("ldmatrix.sync.aligned.m8n8.x2.trans.shared.b16 {%0,%1}, [%2];"
                 : "=r"(r0), "=r"(r1) : "r"(addr));
}
__device__ __forceinline__ void cpa16(uint32_t dst, const void* src) {
    asm volatile("cp.async.cg.shared.global [%0], [%1], 16;" :: "r"(dst), "l"(src));
}
template <int N>
__device__ __forceinline__ void cpa_wait() {
    asm volatile("cp.async.wait_group %0;" :: "n"(N) : "memory");
}
__device__ __forceinline__ void cpa_commit() {
    asm volatile("cp.async.commit_group;" ::: "memory");
}

// ---------------------------------------------------------------------------
// Split kernels: fp32 matrix -> hi/lo bf16-pair arrays. W selects destination.
// 0..2: query/key/value activations; 3..6: q_w/k_w/v_w/o_w weights.
// ---------------------------------------------------------------------------
template <int W>
__global__ __launch_bounds__(256) void split_k(const float4* __restrict__ in, int n4)
{
    int i = blockIdx.x * 256 + threadIdx.x;
    if (i >= n4) return;
    uint2* hi; uint2* lo;
    if      (W == 0) { hi = (uint2*)qa_hi; lo = (uint2*)qa_lo; }
    else if (W == 1) { hi = (uint2*)ka_hi; lo = (uint2*)ka_lo; }
    else if (W == 2) { hi = (uint2*)va_hi; lo = (uint2*)va_lo; }
    else if (W == 3) { hi = (uint2*)qw_hi; lo = (uint2*)qw_lo; }
    else if (W == 4) { hi = (uint2*)kw_hi; lo = (uint2*)kw_lo; }
    else if (W == 5) { hi = (uint2*)vw_hi; lo = (uint2*)vw_lo; }
    else             { hi = (uint2*)ow_hi; lo = (uint2*)ow_lo; }
    float4 f = in[i];
    uint32_t h0, l0, h1, l1;
    split2(f.x, f.y, h0, l0);
    split2(f.z, f.w, h1, l1);
    hi[i] = make_uint2(h0, h1);
    lo[i] = make_uint2(l0, l1);
}

// ---------------------------------------------------------------------------
// 128x128 NT GEMM on pre-split bf16 pairs, bf16x3, cp.async 2-stage, ldmatrix.
// EPI 0/1/2: Q/K/V projection -> gq/gk/gv pair scatter (+bias, +rel for K)
// EPI 4: O proj: ao_pair @ ow_pair^T + bias -> fp32 out
// Dynamic smem bytes (row stride 80B = 20 words, 16 data + 4 pad):
//   Ahi[2] @0 (stage*10240), Alo @20480, Bhi @40960, Blo @61440; total 81920
// ---------------------------------------------------------------------------
template <int EPI>
__global__ __launch_bounds__(256, 2) void gemm_b3(
    const float* __restrict__ bias, const float* __restrict__ rel,
    float* __restrict__ out, int K)
{
    extern __shared__ uint32_t dsm[];

    const uint32_t* Ah = (EPI == 0) ? qa_hi : (EPI == 1) ? ka_hi : (EPI == 2) ? va_hi : ao_hi;
    const uint32_t* Al = (EPI == 0) ? qa_lo : (EPI == 1) ? ka_lo : (EPI == 2) ? va_lo : ao_lo;
    const uint32_t* Bh = (EPI == 0) ? qw_hi : (EPI == 1) ? kw_hi : (EPI == 2) ? vw_hi : ow_hi;
    const uint32_t* Bl = (EPI == 0) ? qw_lo : (EPI == 1) ? kw_lo : (EPI == 2) ? vw_lo : ow_lo;

    const int tid = threadIdx.x;
    const int m0 = blockIdx.y * 128;
    const int n0 = blockIdx.x * 128;
    const int lane = tid & 31, warp = tid >> 5;
    const int wy = warp >> 2, wx = warp & 3;      // 2x4 warp grid: 64x32 per warp
    const int grp = lane >> 2, tig = lane & 3;
    const int K2 = K >> 1;

    uint32_t sbase;
    asm("{.reg .u64 t; cvta.to.shared.u64 t, %1; cvt.u32.u64 %0, t;}"
        : "=r"(sbase) : "l"(dsm));

    float acc[4][4][4];
#pragma unroll
    for (int i = 0; i < 4; i++)
#pragma unroll
        for (int j = 0; j < 4; j++)
#pragma unroll
            for (int r = 0; r < 4; r++) acc[i][j][r] = 0.0f;

    const int nT = K / 32;

    // ldmatrix per-thread base offsets (within a stage buffer)
    const uint32_t aA = (uint32_t)((wy * 64 + (lane & 15)) * 80 + (lane >> 4) * 16);
    const uint32_t aB = (uint32_t)(40960 + (wx * 32 + (lane & 7)) * 80 + ((lane >> 3) & 1) * 16);

    // Fill stage sg with k-tile t
#define GFILL(t, sg)                                                              \
    {                                                                             \
        _Pragma("unroll")                                                         \
        for (int l = 0; l < 2; l++) {                                             \
            int idx = tid + l * 256;                                              \
            int row = idx >> 2, c4 = idx & 3;                                     \
            uint32_t off = (uint32_t)((sg) * 10240 + row * 80 + c4 * 16);         \
            size_t sA = (size_t)(m0 + row) * K2 + (t) * 16 + c4 * 4;              \
            size_t sB = (size_t)(n0 + row) * K2 + (t) * 16 + c4 * 4;              \
            cpa16(sbase + off,         Ah + sA);                                  \
            cpa16(sbase + 20480 + off, Al + sA);                                  \
            cpa16(sbase + 40960 + off, Bh + sB);                                  \
            cpa16(sbase + 61440 + off, Bl + sB);                                  \
        }                                                                         \
        cpa_commit();                                                             \
    }

    GFILL(0, 0);

    for (int t = 0; t < nT; t++) {
        const int st = t & 1;
        if (t + 1 < nT) { GFILL(t + 1, st ^ 1); cpa_wait<1>(); }
        else            { cpa_wait<0>(); }
        __syncthreads();

        const uint32_t sb = sbase + st * 10240;
#pragma unroll
        for (int ks = 0; ks < 2; ks++) {
            uint32_t bh[4][2], bl[4][2];
#pragma unroll
            for (int j = 0; j < 4; j++) {
                ldmat_x2(bh[j][0], bh[j][1], sb + aB + j * 640 + ks * 32);
                ldmat_x2(bl[j][0], bl[j][1], sb + aB + 20480 + j * 640 + ks * 32);
            }
#pragma unroll
            for (int i = 0; i < 4; i++) {
                uint32_t ah[4], al[4];
                ldmat_x4(ah, sb + aA + i * 1280 + ks * 32);
                ldmat_x4(al, sb + aA + 20480 + i * 1280 + ks * 32);
#pragma unroll
                for (int j = 0; j < 4; j++) {
                    mma_bf16(acc[i][j], ah, bh[j]);
                    mma_bf16(acc[i][j], al, bh[j]);
                    mma_bf16(acc[i][j], ah, bl[j]);
                }
            }
        }
        __syncthreads();
    }
#undef GFILL

    // Epilogue
    uint32_t* Dh = (EPI == 0) ? gq_hi : (EPI == 1) ? gk_hi : gv_hi;
    uint32_t* Dl = (EPI == 0) ? gq_lo : (EPI == 1) ? gk_lo : gv_lo;
#pragma unroll
    for (int i = 0; i < 4; i++) {
        int mrow = m0 + wy * 64 + i * 16 + grp;
#pragma unroll
        for (int j = 0; j < 4; j++) {
            int ne = n0 + wx * 32 + j * 8 + 2 * tig;   // even column
            if constexpr (EPI <= 2) {
                int h = ne >> 6, dl = ne & 63, dw = dl >> 1;
                float b0 = bias[ne], b1 = bias[ne + 1];
#pragma unroll
                for (int half = 0; half < 2; half++) {
                    int m = mrow + half * 8;
                    int bb = m >> 10, tt = m & 1023;
                    float v0 = acc[i][j][2 * half]     + b0;
                    float v1 = acc[i][j][2 * half + 1] + b1;
                    if constexpr (EPI == 1) {
                        v0 += rel[((size_t)h * MAXLEN + tt) * D_ + dl];
                        v1 += rel[((size_t)h * MAXLEN + tt) * D_ + dl + 1];
                    }
                    uint32_t hw, lw;
                    split2(v0, v1, hw, lw);
                    size_t di = ((size_t)(bb * H_ + h) * T_ + tt) * 32 + dw;
                    Dh[di] = hw;
                    Dl[di] = lw;
                }
            } else {
                float b0 = bias[ne], b1 = bias[ne + 1];
                out[(size_t)mrow * E_ + ne]           = acc[i][j][0] + b0;
                out[(size_t)mrow * E_ + ne + 1]       = acc[i][j][1] + b1;
                out[(size_t)(mrow + 8) * E_ + ne]     = acc[i][j][2] + b0;
                out[(size_t)(mrow + 8) * E_ + ne + 1] = acc[i][j][3] + b1;
            }
        }
    }
}

// ---------------------------------------------------------------------------
// Fused flash attention on pre-split q/k/v pairs. Output -> ao pair arrays.
// Smem (u32 words): Qhi[128][36] @0, Qlo @4608, Khi[64][36] @9216, Klo @11520,
//                   Vhi[64][36] @13824, Vlo @16128   (73728 B total)
// ---------------------------------------------------------------------------
__global__ __launch_bounds__(256, 2) void flash_attn(const unsigned char* __restrict__ mask)
{
    extern __shared__ uint32_t sm[];
    uint32_t* Qhi = sm;
    uint32_t* Qlo = sm + 4608;
    uint32_t* Khi = sm + 9216;
    uint32_t* Klo = sm + 11520;

    const int tid = threadIdx.x;
    const int lane = tid & 31, warp = tid >> 5;
    const int grp = lane >> 2, tig = lane & 3;
    const int m0 = blockIdx.x * 128;
    const int z  = blockIdx.y;
    const int bb = z >> 4, h = z & 15;

    const unsigned char* mrow_g = mask + (size_t)bb * S_;

    uint32_t sbase;
    asm("{.reg .u64 t; cvta.to.shared.u64 t, %1; cvt.u32.u64 %0, t;}"
        : "=r"(sbase) : "l"(sm));
    const uint32_t vrow_h = sbase + 55296 + (lane & 15) * 144;  // Vhi + row*144

    // Q fill (cp.async): 128 rows x 32 words (hi + lo)
#pragma unroll
    for (int l = 0; l < 4; l++) {
        int idx = tid + l * 256;
        int row = idx >> 3, c4 = idx & 7;
        uint32_t off = (uint32_t)(row * 144 + c4 * 16);
        size_t src = ((size_t)z * T_ + m0 + row) * 32 + c4 * 4;
        cpa16(sbase + off,         gq_hi + src);
        cpa16(sbase + 18432 + off, gq_lo + src);
    }

    float accO[8][4];
#pragma unroll
    for (int jd = 0; jd < 8; jd++)
#pragma unroll
        for (int r = 0; r < 4; r++) accO[jd][r] = 0.0f;
    float m0r = -1e29f, m1r = -1e29f, l0r = 0.0f, l1r = 0.0f;

    const int r0 = warp * 16 + grp;

    for (int s0 = 0; s0 < S_; s0 += 64) {
        // K/V fill (cp.async): 64 rows x 32 words each, hi + lo
#pragma unroll
        for (int l = 0; l < 2; l++) {
            int idx = tid + l * 256;
            int row = idx >> 3, c4 = idx & 7;
            uint32_t off = (uint32_t)(row * 144 + c4 * 16);
            size_t src = ((size_t)z * S_ + s0 + row) * 32 + c4 * 4;
            cpa16(sbase + 36864 + off, gk_hi + src);
            cpa16(sbase + 46080 + off, gk_lo + src);
            cpa16(sbase + 55296 + off, gv_hi + src);
            cpa16(sbase + 64512 + off, gv_lo + src);
        }
        cpa_commit();
        cpa_wait<0>();
        __syncthreads();

        // Scores: warp's 16 rows x 64 cols, bf16x3
        float acc[8][4];
#pragma unroll
        for (int j = 0; j < 8; j++)
#pragma unroll
            for (int r = 0; r < 4; r++) acc[j][r] = 0.0f;

#pragma unroll
        for (int ks = 0; ks < 4; ks++) {
            const int kb = ks * 8;
            uint32_t qh[4], ql[4];
            qh[0] = Qhi[r0 * 36 + kb + tig];
            qh[1] = Qhi[(r0 + 8) * 36 + kb + tig];
            qh[2] = Qhi[r0 * 36 + kb + tig + 4];
            qh[3] = Qhi[(r0 + 8) * 36 + kb + tig + 4];
            ql[0] = Qlo[r0 * 36 + kb + tig];
            ql[1] = Qlo[(r0 + 8) * 36 + kb + tig];
            ql[2] = Qlo[r0 * 36 + kb + tig + 4];
            ql[3] = Qlo[(r0 + 8) * 36 + kb + tig + 4];
#pragma unroll
            for (int j = 0; j < 8; j++) {
                int c0 = j * 8 + grp;
                uint32_t kh[2], kl[2];
                kh[0] = Khi[c0 * 36 + kb + tig];
                kh[1] = Khi[c0 * 36 + kb + tig + 4];
                kl[0] = Klo[c0 * 36 + kb + tig];
                kl[1] = Klo[c0 * 36 + kb + tig + 4];
                mma_bf16(acc[j], qh, kh);
                mma_bf16(acc[j], ql, kh);
                mma_bf16(acc[j], qh, kl);
            }
        }

        // Mask
#pragma unroll
        for (int j = 0; j < 8; j++) {
            int c = s0 + j * 8 + 2 * tig;
            if (mrow_g[c])     { acc[j][0] = neg_big(); acc[j][2] = neg_big(); }
            if (mrow_g[c + 1]) { acc[j][1] = neg_big(); acc[j][3] = neg_big(); }
        }

        // Online softmax
        float tm0 = neg_big(), tm1 = neg_big();
#pragma unroll
        for (int j = 0; j < 8; j++) {
            tm0 = fmaxf(tm0, fmaxf(acc[j][0], acc[j][1]));
            tm1 = fmaxf(tm1, fmaxf(acc[j][2], acc[j][3]));
        }
        tm0 = fmaxf(tm0, __shfl_xor_sync(0xffffffffu, tm0, 1));
        tm0 = fmaxf(tm0, __shfl_xor_sync(0xffffffffu, tm0, 2));
        tm1 = fmaxf(tm1, __shfl_xor_sync(0xffffffffu, tm1, 1));
        tm1 = fmaxf(tm1, __shfl_xor_sync(0xffffffffu, tm1, 2));

        float mn0 = fmaxf(fmaxf(m0r, tm0), -1e29f);
        float mn1 = fmaxf(fmaxf(m1r, tm1), -1e29f);
        float sc0 = __expf(m0r - mn0);
        float sc1 = __expf(m1r - mn1);

        float ts0 = 0.0f, ts1 = 0.0f;
#pragma unroll
        for (int j = 0; j < 8; j++) {
            acc[j][0] = __expf(acc[j][0] - mn0);
            acc[j][1] = __expf(acc[j][1] - mn0);
            acc[j][2] = __expf(acc[j][2] - mn1);
            acc[j][3] = __expf(acc[j][3] - mn1);
            ts0 += acc[j][0] + acc[j][1];
            ts1 += acc[j][2] + acc[j][3];
        }
        ts0 += __shfl_xor_sync(0xffffffffu, ts0, 1);
        ts0 += __shfl_xor_sync(0xffffffffu, ts0, 2);
        ts1 += __shfl_xor_sync(0xffffffffu, ts1, 1);
        ts1 += __shfl_xor_sync(0xffffffffu, ts1, 2);

        l0r = l0r * sc0 + ts0;
        l1r = l1r * sc1 + ts1;
        m0r = mn0; m1r = mn1;

#pragma unroll
        for (int jd = 0; jd < 8; jd++) {
            accO[jd][0] *= sc0; accO[jd][1] *= sc0;
            accO[jd][2] *= sc1; accO[jd][3] *= sc1;
        }

        // PV: register-split probs @ V (ldmatrix.trans), bf16x3
#pragma unroll
        for (int ks = 0; ks < 4; ks++) {
            uint32_t ah[4], al[4];
            split2(acc[2 * ks][0],     acc[2 * ks][1],     ah[0], al[0]);
            split2(acc[2 * ks][2],     acc[2 * ks][3],     ah[1], al[1]);
            split2(acc[2 * ks + 1][0], acc[2 * ks + 1][1], ah[2], al[2]);
            split2(acc[2 * ks + 1][2], acc[2 * ks + 1][3], ah[3], al[3]);
            uint32_t rbase = vrow_h + ks * 2304;
#pragma unroll
            for (int jd = 0; jd < 8; jd++) {
                uint32_t bh[2], bl[2];
                ldmat_x2_trans(bh[0], bh[1], rbase + jd * 16);
                ldmat_x2_trans(bl[0], bl[1], rbase + jd * 16 + 9216);
                mma_bf16(accO[jd], ah, bh);
                mma_bf16(accO[jd], al, bh);
                mma_bf16(accO[jd], ah, bl);
            }
        }
        __syncthreads();
    }

    // Epilogue: normalized O -> ao pair arrays [4096][512]
    float inv0 = 1.0f / l0r, inv1 = 1.0f / l1r;
    size_t row0 = (size_t)bb * T_ + m0 + warp * 16 + grp;
    size_t row1 = row0 + 8;
#pragma unroll
    for (int jd = 0; jd < 8; jd++) {
        int w = h * 32 + jd * 4 + tig;   // pair-word index within E/2
        uint32_t hw, lw;
        split2(accO[jd][0] * inv0, accO[jd][1] * inv0, hw, lw);
        ao_hi[row0 * 512 + w] = hw;
        ao_lo[row0 * 512 + w] = lw;
        split2(accO[jd][2] * inv1, accO[jd][3] * inv1, hw, lw);
        ao_hi[row1 * 512 + w] = hw;
        ao_lo[row1 * 512 + w] = lw;
    }
}

extern "C" void kernel_launch(void* const* d_in, const int* in_sizes, int n_in,
                              void* d_out, int out_size)
{
    const float* query = (const float*)d_in[0];
    const float* key   = (const float*)d_in[1];
    const float* value = (const float*)d_in[2];
    const unsigned char* mask = (const unsigned char*)d_in[3];
    const float* q_w = (const float*)d_in[4];
    const float* q_b = (const float*)d_in[5];
    const float* k_w = (const float*)d_in[6];
    const float* k_b = (const float*)d_in[7];
    const float* v_w = (const float*)d_in[8];
    const float* v_b = (const float*)d_in[9];
    const float* o_w = (const float*)d_in[10];
    const float* o_b = (const float*)d_in[11];
    const float* rel = (const float*)d_in[12];
    float* out = (float*)d_out;

    const int GSMEM = 81920;
    cudaFuncSetAttribute(gemm_b3<0>, cudaFuncAttributeMaxDynamicSharedMemorySize, GSMEM);
    cudaFuncSetAttribute(gemm_b3<1>, cudaFuncAttributeMaxDynamicSharedMemorySize, GSMEM);
    cudaFuncSetAttribute(gemm_b3<2>, cudaFuncAttributeMaxDynamicSharedMemorySize, GSMEM);
    cudaFuncSetAttribute(gemm_b3<4>, cudaFuncAttributeMaxDynamicSharedMemorySize, GSMEM);
    cudaFuncSetAttribute(flash_attn, cudaFuncAttributeMaxDynamicSharedMemorySize, 73728);

    // Pre-split inputs
    const int nA = 4096 * 1024 / 4;   // activations, float4 count
    const int nW = 1024 * 1024 / 4;   // weights
    split_k<0><<<nA / 256, 256>>>((const float4*)query, nA);
    split_k<1><<<nA / 256, 256>>>((const float4*)key,   nA);
    split_k<2><<<nA / 256, 256>>>((const float4*)value, nA);
    split_k<3><<<nW / 256, 256>>>((const float4*)q_w, nW);
    split_k<4><<<nW / 256, 256>>>((const float4*)k_w, nW);
    split_k<5><<<nW / 256, 256>>>((const float4*)v_w, nW);
    split_k<6><<<nW / 256, 256>>>((const float4*)o_w, nW);

    dim3 pg(E_ / 128, (B_ * T_) / 128, 1);
    gemm_b3<0><<<pg, 256, GSMEM>>>(q_b, nullptr, nullptr, E_);
    gemm_b3<1><<<pg, 256, GSMEM>>>(k_b, rel,     nullptr, E_);
    gemm_b3<2><<<pg, 256, GSMEM>>>(v_b, nullptr, nullptr, E_);

    dim3 fg(T_ / 128, B_ * H_, 1);
    flash_attn<<<fg, 256, 73728>>>(mask);

    dim3 og(E_ / 128, (B_ * T_) / 128, 1);
    gemm_b3<4><<<og, 256, GSMEM>>>(o_b, nullptr, out, E_);
}

// round 10
// speedup vs baseline: 3.0405x; 1.0316x over previous
#include <cuda_runtime.h>
#include <cuda_bf16.h>
#include <math.h>
#include <stdint.h>

#define B_ 4
#define T_ 1024
#define S_ 1024
#define E_ 1024
#define H_ 16
#define D_ 64
#define MAXLEN 2048

// ---------------- Pre-split bf16-pair device globals ----------------
// Activations [4096][512] pair-words (pairs along K)
__device__ uint32_t qa_hi[4096 * 512], qa_lo[4096 * 512];
__device__ uint32_t ka_hi[4096 * 512], ka_lo[4096 * 512];
__device__ uint32_t va_hi[4096 * 512], va_lo[4096 * 512];
__device__ uint32_t ao_hi[4096 * 512], ao_lo[4096 * 512];   // attention out (pair)
// Weights [1024][512]
__device__ uint32_t qw_hi[1024 * 512], qw_lo[1024 * 512];
__device__ uint32_t kw_hi[1024 * 512], kw_lo[1024 * 512];
__device__ uint32_t vw_hi[1024 * 512], vw_lo[1024 * 512];
__device__ uint32_t ow_hi[1024 * 512], ow_lo[1024 * 512];
// Projected q/k/v: [z][t][32] pair-words (pairs along d), z = b*16+h
__device__ uint32_t gq_hi[64 * 1024 * 32], gq_lo[64 * 1024 * 32];
__device__ uint32_t gk_hi[64 * 1024 * 32], gk_lo[64 * 1024 * 32];
__device__ uint32_t gv_hi[64 * 1024 * 32], gv_lo[64 * 1024 * 32];

__device__ __forceinline__ float neg_big() { return -1e30f; }

__device__ __forceinline__ void split2(float x, float y, uint32_t& hi, uint32_t& lo) {
    __nv_bfloat16 xh = __float2bfloat16(x);
    __nv_bfloat16 yh = __float2bfloat16(y);
    __nv_bfloat16 xl = __float2bfloat16(x - __bfloat162float(xh));
    __nv_bfloat16 yl = __float2bfloat16(y - __bfloat162float(yh));
    hi = (uint32_t)__bfloat16_as_ushort(xh) | ((uint32_t)__bfloat16_as_ushort(yh) << 16);
    lo = (uint32_t)__bfloat16_as_ushort(xl) | ((uint32_t)__bfloat16_as_ushort(yl) << 16);
}

__device__ __forceinline__ void mma_bf16(float c[4], const uint32_t a[4], const uint32_t b[2]) {
    asm volatile(
        "mma.sync.aligned.m16n8k16.row.col.f32.bf16.bf16.f32 "
        "{%0,%1,%2,%3}, {%4,%5,%6,%7}, {%8,%9}, {%0,%1,%2,%3};"
        : "+f"(c[0]), "+f"(c[1]), "+f"(c[2]), "+f"(c[3])
        : "r"(a[0]), "r"(a[1]), "r"(a[2]), "r"(a[3]), "r"(b[0]), "r"(b[1]));
}

__device__ __forceinline__ void ldmat_x4(uint32_t r[4], uint32_t addr) {
    asm volatile("ldmatrix.sync.aligned.m8n8.x4.shared.b16 {%0,%1,%2,%3}, [%4];"
                 : "=r"(r[0]), "=r"(r[1]), "=r"(r[2]), "=r"(r[3]) : "r"(addr));
}
__device__ __forceinline__ void ldmat_x2(uint32_t& r0, uint32_t& r1, uint32_t addr) {
    asm volatile("ldmatrix.sync.aligned.m8n8.x2.shared.b16 {%0,%1}, [%2];"
                 : "=r"(r0), "=r"(r1) : "r"(addr));
}
__device__ __forceinline__ void ldmat_x2_trans(uint32_t& r0, uint32_t& r1, uint32_t addr) {
    asm volatile("ldmatrix.sync.aligned.m8n8.x2.trans.shared.b16 {%0,%1}, [%2];"
                 : "=r"(r0), "=r"(r1) : "r"(addr));
}
__device__ __forceinline__ void cpa16(uint32_t dst, const void* src) {
    asm volatile("cp.async.cg.shared.global [%0], [%1], 16;" :: "r"(dst), "l"(src));
}
template <int N>
__device__ __forceinline__ void cpa_wait() {
    asm volatile("cp.async.wait_group %0;" :: "n"(N) : "memory");
}
__device__ __forceinline__ void cpa_commit() {
    asm volatile("cp.async.commit_group;" ::: "memory");
}

// ---------------------------------------------------------------------------
// One merged split kernel: all 3 activations + 4 weights in a single launch.
// Segments (float4 units): qa/ka/va 1048576 each, then qw/kw/vw/ow 262144 each.
// ---------------------------------------------------------------------------
#define NA4 (4096 * 1024 / 4)
#define NW4 (1024 * 1024 / 4)
__global__ __launch_bounds__(256) void split_all(
    const float4* __restrict__ q,  const float4* __restrict__ k,
    const float4* __restrict__ v,  const float4* __restrict__ qw,
    const float4* __restrict__ kw, const float4* __restrict__ vw,
    const float4* __restrict__ ow)
{
    int i = blockIdx.x * 256 + threadIdx.x;
    const float4* src;
    uint2 *hi, *lo;
    int li = i;
    if (li < 3 * NA4) {
        int seg = li / NA4; li -= seg * NA4;
        src = (seg == 0) ? q : (seg == 1) ? k : v;
        hi = (uint2*)((seg == 0) ? qa_hi : (seg == 1) ? ka_hi : va_hi);
        lo = (uint2*)((seg == 0) ? qa_lo : (seg == 1) ? ka_lo : va_lo);
    } else {
        li -= 3 * NA4;
        int seg = li / NW4; li -= seg * NW4;
        src = (seg == 0) ? qw : (seg == 1) ? kw : (seg == 2) ? vw : ow;
        hi = (uint2*)((seg == 0) ? qw_hi : (seg == 1) ? kw_hi : (seg == 2) ? vw_hi : ow_hi);
        lo = (uint2*)((seg == 0) ? qw_lo : (seg == 1) ? kw_lo : (seg == 2) ? vw_lo : ow_lo);
    }
    float4 f = src[li];
    uint32_t h0, l0, h1, l1;
    split2(f.x, f.y, h0, l0);
    split2(f.z, f.w, h1, l1);
    hi[li] = make_uint2(h0, h1);
    lo[li] = make_uint2(l0, l1);
}

// ---------------------------------------------------------------------------
// GEMM mainloop shared by the two GEMM kernels (macro to keep one source of
// truth). Computes acc[4][4][4] for a 128x128 tile from pre-split pairs.
// ---------------------------------------------------------------------------
#define GEMM_BODY(Ah, Al, Bh, Bl, K)                                              \
    const int lane = tid & 31, warp = tid >> 5;                                   \
    const int wy = warp >> 2, wx = warp & 3;                                      \
    const int grp = lane >> 2, tig = lane & 3;                                    \
    const int K2 = (K) >> 1;                                                      \
    uint32_t sbase;                                                               \
    asm("{.reg .u64 t; cvta.to.shared.u64 t, %1; cvt.u32.u64 %0, t;}"             \
        : "=r"(sbase) : "l"(dsm));                                                \
    float acc[4][4][4];                                                           \
    _Pragma("unroll")                                                             \
    for (int i = 0; i < 4; i++)                                                   \
        _Pragma("unroll")                                                         \
        for (int j = 0; j < 4; j++)                                               \
            _Pragma("unroll")                                                     \
            for (int r = 0; r < 4; r++) acc[i][j][r] = 0.0f;                      \
    const int nT = (K) / 32;                                                      \
    const uint32_t aA = (uint32_t)((wy * 64 + (lane & 15)) * 80 + (lane >> 4) * 16);       \
    const uint32_t aB = (uint32_t)(40960 + (wx * 32 + (lane & 7)) * 80 + ((lane >> 3) & 1) * 16); \
    {                                                                             \
        _Pragma("unroll")                                                         \
        for (int l = 0; l < 2; l++) {                                             \
            int idx = tid + l * 256;                                              \
            int row = idx >> 2, c4 = idx & 3;                                     \
            uint32_t off = (uint32_t)(row * 80 + c4 * 16);                        \
            size_t sA = (size_t)(m0 + row) * K2 + c4 * 4;                         \
            size_t sB = (size_t)(n0 + row) * K2 + c4 * 4;                         \
            cpa16(sbase + off,         (Ah) + sA);                                \
            cpa16(sbase + 20480 + off, (Al) + sA);                                \
            cpa16(sbase + 40960 + off, (Bh) + sB);                                \
            cpa16(sbase + 61440 + off, (Bl) + sB);                                \
        }                                                                         \
        cpa_commit();                                                             \
    }                                                                             \
    for (int t = 0; t < nT; t++) {                                                \
        const int st = t & 1;                                                     \
        if (t + 1 < nT) {                                                         \
            _Pragma("unroll")                                                     \
            for (int l = 0; l < 2; l++) {                                         \
                int idx = tid + l * 256;                                          \
                int row = idx >> 2, c4 = idx & 3;                                 \
                uint32_t off = (uint32_t)((st ^ 1) * 10240 + row * 80 + c4 * 16); \
                size_t sA = (size_t)(m0 + row) * K2 + (t + 1) * 16 + c4 * 4;      \
                size_t sB = (size_t)(n0 + row) * K2 + (t + 1) * 16 + c4 * 4;      \
                cpa16(sbase + off,         (Ah) + sA);                            \
                cpa16(sbase + 20480 + off, (Al) + sA);                            \
                cpa16(sbase + 40960 + off, (Bh) + sB);                            \
                cpa16(sbase + 61440 + off, (Bl) + sB);                            \
            }                                                                     \
            cpa_commit();                                                         \
            cpa_wait<1>();                                                        \
        } else {                                                                  \
            cpa_wait<0>();                                                        \
        }                                                                         \
        __syncthreads();                                                          \
        const uint32_t sb = sbase + st * 10240;                                   \
        _Pragma("unroll")                                                         \
        for (int ks = 0; ks < 2; ks++) {                                          \
            uint32_t bh[4][2], bl[4][2];                                          \
            _Pragma("unroll")                                                     \
            for (int j = 0; j < 4; j++) {                                         \
                ldmat_x2(bh[j][0], bh[j][1], sb + aB + j * 640 + ks * 32);        \
                ldmat_x2(bl[j][0], bl[j][1], sb + aB + 20480 + j * 640 + ks * 32);\
            }                                                                     \
            _Pragma("unroll")                                                     \
            for (int i = 0; i < 4; i++) {                                         \
                uint32_t ah[4], al[4];                                            \
                ldmat_x4(ah, sb + aA + i * 1280 + ks * 32);                       \
                ldmat_x4(al, sb + aA + 20480 + i * 1280 + ks * 32);               \
                _Pragma("unroll")                                                 \
                for (int j = 0; j < 4; j++) {                                     \
                    mma_bf16(acc[i][j], ah, bh[j]);                               \
                    mma_bf16(acc[i][j], al, bh[j]);                               \
                    mma_bf16(acc[i][j], ah, bl[j]);                               \
                }                                                                 \
            }                                                                     \
        }                                                                         \
        __syncthreads();                                                          \
    }

// ---------------------------------------------------------------------------
// Merged Q/K/V projection GEMM: blockIdx.z in {0,1,2} selects the projection.
// 768 blocks in one launch -> full machine waves.
// ---------------------------------------------------------------------------
__global__ __launch_bounds__(256, 2) void proj_qkv(
    const float* __restrict__ q_b, const float* __restrict__ k_b,
    const float* __restrict__ v_b, const float* __restrict__ rel)
{
    extern __shared__ uint32_t dsm[];
    const int which = blockIdx.z;
    const int tid = threadIdx.x;
    const int m0 = blockIdx.y * 128;
    const int n0 = blockIdx.x * 128;

    const uint32_t* Ah = (which == 0) ? qa_hi : (which == 1) ? ka_hi : va_hi;
    const uint32_t* Al = (which == 0) ? qa_lo : (which == 1) ? ka_lo : va_lo;
    const uint32_t* Bh = (which == 0) ? qw_hi : (which == 1) ? kw_hi : vw_hi;
    const uint32_t* Bl = (which == 0) ? qw_lo : (which == 1) ? kw_lo : vw_lo;
    const float* bias  = (which == 0) ? q_b : (which == 1) ? k_b : v_b;
    uint32_t* Dh = (which == 0) ? gq_hi : (which == 1) ? gk_hi : gv_hi;
    uint32_t* Dl = (which == 0) ? gq_lo : (which == 1) ? gk_lo : gv_lo;

    GEMM_BODY(Ah, Al, Bh, Bl, E_)

#pragma unroll
    for (int i = 0; i < 4; i++) {
        int mrow = m0 + wy * 64 + i * 16 + grp;
#pragma unroll
        for (int j = 0; j < 4; j++) {
            int ne = n0 + wx * 32 + j * 8 + 2 * tig;
            int h = ne >> 6, dl = ne & 63, dw = dl >> 1;
            float b0 = bias[ne], b1 = bias[ne + 1];
#pragma unroll
            for (int half = 0; half < 2; half++) {
                int m = mrow + half * 8;
                int bb = m >> 10, tt = m & 1023;
                float v0 = acc[i][j][2 * half]     + b0;
                float v1 = acc[i][j][2 * half + 1] + b1;
                if (which == 1) {
                    v0 += rel[((size_t)h * MAXLEN + tt) * D_ + dl];
                    v1 += rel[((size_t)h * MAXLEN + tt) * D_ + dl + 1];
                }
                uint32_t hw, lw;
                split2(v0, v1, hw, lw);
                size_t di = ((size_t)(bb * H_ + h) * T_ + tt) * 32 + dw;
                Dh[di] = hw;
                Dl[di] = lw;
            }
        }
    }
}

// ---------------------------------------------------------------------------
// O projection GEMM: ao_pair @ ow_pair^T + bias -> fp32 out
// ---------------------------------------------------------------------------
__global__ __launch_bounds__(256, 2) void proj_o(
    const float* __restrict__ bias, float* __restrict__ out)
{
    extern __shared__ uint32_t dsm[];
    const int tid = threadIdx.x;
    const int m0 = blockIdx.y * 128;
    const int n0 = blockIdx.x * 128;

    GEMM_BODY(ao_hi, ao_lo, ow_hi, ow_lo, E_)

#pragma unroll
    for (int i = 0; i < 4; i++) {
        int mrow = m0 + wy * 64 + i * 16 + grp;
#pragma unroll
        for (int j = 0; j < 4; j++) {
            int ne = n0 + wx * 32 + j * 8 + 2 * tig;
            float b0 = bias[ne], b1 = bias[ne + 1];
            out[(size_t)mrow * E_ + ne]           = acc[i][j][0] + b0;
            out[(size_t)mrow * E_ + ne + 1]       = acc[i][j][1] + b1;
            out[(size_t)(mrow + 8) * E_ + ne]     = acc[i][j][2] + b0;
            out[(size_t)(mrow + 8) * E_ + ne + 1] = acc[i][j][3] + b1;
        }
    }
}

// ---------------------------------------------------------------------------
// Fused flash attention on pre-split q/k/v pairs. Output -> ao pair arrays.
// Smem (u32 words): Qhi[128][36] @0, Qlo @4608, Khi[64][36] @9216, Klo @11520,
//                   Vhi[64][36] @13824, Vlo @16128   (73728 B total)
// ---------------------------------------------------------------------------
__global__ __launch_bounds__(256, 2) void flash_attn(const unsigned char* __restrict__ mask)
{
    extern __shared__ uint32_t sm[];
    uint32_t* Qhi = sm;
    uint32_t* Qlo = sm + 4608;
    uint32_t* Khi = sm + 9216;
    uint32_t* Klo = sm + 11520;

    const int tid = threadIdx.x;
    const int lane = tid & 31, warp = tid >> 5;
    const int grp = lane >> 2, tig = lane & 3;
    const int m0 = blockIdx.x * 128;
    const int z  = blockIdx.y;
    const int bb = z >> 4, h = z & 15;

    const unsigned char* mrow_g = mask + (size_t)bb * S_;

    uint32_t sbase;
    asm("{.reg .u64 t; cvta.to.shared.u64 t, %1; cvt.u32.u64 %0, t;}"
        : "=r"(sbase) : "l"(sm));
    const uint32_t vrow_h = sbase + 55296 + (lane & 15) * 144;

    // Q fill (cp.async): 128 rows x 32 words (hi + lo)
#pragma unroll
    for (int l = 0; l < 4; l++) {
        int idx = tid + l * 256;
        int row = idx >> 3, c4 = idx & 7;
        uint32_t off = (uint32_t)(row * 144 + c4 * 16);
        size_t src = ((size_t)z * T_ + m0 + row) * 32 + c4 * 4;
        cpa16(sbase + off,         gq_hi + src);
        cpa16(sbase + 18432 + off, gq_lo + src);
    }

    float accO[8][4];
#pragma unroll
    for (int jd = 0; jd < 8; jd++)
#pragma unroll
        for (int r = 0; r < 4; r++) accO[jd][r] = 0.0f;
    float m0r = -1e29f, m1r = -1e29f, l0r = 0.0f, l1r = 0.0f;

    const int r0 = warp * 16 + grp;

    for (int s0 = 0; s0 < S_; s0 += 64) {
#pragma unroll
        for (int l = 0; l < 2; l++) {
            int idx = tid + l * 256;
            int row = idx >> 3, c4 = idx & 7;
            uint32_t off = (uint32_t)(row * 144 + c4 * 16);
            size_t src = ((size_t)z * S_ + s0 + row) * 32 + c4 * 4;
            cpa16(sbase + 36864 + off, gk_hi + src);
            cpa16(sbase + 46080 + off, gk_lo + src);
            cpa16(sbase + 55296 + off, gv_hi + src);
            cpa16(sbase + 64512 + off, gv_lo + src);
        }
        cpa_commit();
        cpa_wait<0>();
        __syncthreads();

        float acc[8][4];
#pragma unroll
        for (int j = 0; j < 8; j++)
#pragma unroll
            for (int r = 0; r < 4; r++) acc[j][r] = 0.0f;

#pragma unroll
        for (int ks = 0; ks < 4; ks++) {
            const int kb = ks * 8;
            uint32_t qh[4], ql[4];
            qh[0] = Qhi[r0 * 36 + kb + tig];
            qh[1] = Qhi[(r0 + 8) * 36 + kb + tig];
            qh[2] = Qhi[r0 * 36 + kb + tig + 4];
            qh[3] = Qhi[(r0 + 8) * 36 + kb + tig + 4];
            ql[0] = Qlo[r0 * 36 + kb + tig];
            ql[1] = Qlo[(r0 + 8) * 36 + kb + tig];
            ql[2] = Qlo[r0 * 36 + kb + tig + 4];
            ql[3] = Qlo[(r0 + 8) * 36 + kb + tig + 4];
#pragma unroll
            for (int j = 0; j < 8; j++) {
                int c0 = j * 8 + grp;
                uint32_t kh[2], kl[2];
                kh[0] = Khi[c0 * 36 + kb + tig];
                kh[1] = Khi[c0 * 36 + kb + tig + 4];
                kl[0] = Klo[c0 * 36 + kb + tig];
                kl[1] = Klo[c0 * 36 + kb + tig + 4];
                mma_bf16(acc[j], qh, kh);
                mma_bf16(acc[j], ql, kh);
                mma_bf16(acc[j], qh, kl);
            }
        }

#pragma unroll
        for (int j = 0; j < 8; j++) {
            int c = s0 + j * 8 + 2 * tig;
            if (mrow_g[c])     { acc[j][0] = neg_big(); acc[j][2] = neg_big(); }
            if (mrow_g[c + 1]) { acc[j][1] = neg_big(); acc[j][3] = neg_big(); }
        }

        float tm0 = neg_big(), tm1 = neg_big();
#pragma unroll
        for (int j = 0; j < 8; j++) {
            tm0 = fmaxf(tm0, fmaxf(acc[j][0], acc[j][1]));
            tm1 = fmaxf(tm1, fmaxf(acc[j][2], acc[j][3]));
        }
        tm0 = fmaxf(tm0, __shfl_xor_sync(0xffffffffu, tm0, 1));
        tm0 = fmaxf(tm0, __shfl_xor_sync(0xffffffffu, tm0, 2));
        tm1 = fmaxf(tm1, __shfl_xor_sync(0xffffffffu, tm1, 1));
        tm1 = fmaxf(tm1, __shfl_xor_sync(0xffffffffu, tm1, 2));

        float mn0 = fmaxf(fmaxf(m0r, tm0), -1e29f);
        float mn1 = fmaxf(fmaxf(m1r, tm1), -1e29f);
        float sc0 = __expf(m0r - mn0);
        float sc1 = __expf(m1r - mn1);

        float ts0 = 0.0f, ts1 = 0.0f;
#pragma unroll
        for (int j = 0; j < 8; j++) {
            acc[j][0] = __expf(acc[j][0] - mn0);
            acc[j][1] = __expf(acc[j][1] - mn0);
            acc[j][2] = __expf(acc[j][2] - mn1);
            acc[j][3] = __expf(acc[j][3] - mn1);
            ts0 += acc[j][0] + acc[j][1];
            ts1 += acc[j][2] + acc[j][3];
        }
        ts0 += __shfl_xor_sync(0xffffffffu, ts0, 1);
        ts0 += __shfl_xor_sync(0xffffffffu, ts0, 2);
        ts1 += __shfl_xor_sync(0xffffffffu, ts1, 1);
        ts1 += __shfl_xor_sync(0xffffffffu, ts1, 2);

        l0r = l0r * sc0 + ts0;
        l1r = l1r * sc1 + ts1;
        m0r = mn0; m1r = mn1;

#pragma unroll
        for (int jd = 0; jd < 8; jd++) {
            accO[jd][0] *= sc0; accO[jd][1] *= sc0;
            accO[jd][2] *= sc1; accO[jd][3] *= sc1;
        }

#pragma unroll
        for (int ks = 0; ks < 4; ks++) {
            uint32_t ah[4], al[4];
            split2(acc[2 * ks][0],     acc[2 * ks][1],     ah[0], al[0]);
            split2(acc[2 * ks][2],     acc[2 * ks][3],     ah[1], al[1]);
            split2(acc[2 * ks + 1][0], acc[2 * ks + 1][1], ah[2], al[2]);
            split2(acc[2 * ks + 1][2], acc[2 * ks + 1][3], ah[3], al[3]);
            uint32_t rbase = vrow_h + ks * 2304;
#pragma unroll
            for (int jd = 0; jd < 8; jd++) {
                uint32_t bh[2], bl[2];
                ldmat_x2_trans(bh[0], bh[1], rbase + jd * 16);
                ldmat_x2_trans(bl[0], bl[1], rbase + jd * 16 + 9216);
                mma_bf16(accO[jd], ah, bh);
                mma_bf16(accO[jd], al, bh);
                mma_bf16(accO[jd], ah, bl);
            }
        }
        __syncthreads();
    }

    float inv0 = 1.0f / l0r, inv1 = 1.0f / l1r;
    size_t row0 = (size_t)bb * T_ + m0 + warp * 16 + grp;
    size_t row1 = row0 + 8;
#pragma unroll
    for (int jd = 0; jd < 8; jd++) {
        int w = h * 32 + jd * 4 + tig;
        uint32_t hw, lw;
        split2(accO[jd][0] * inv0, accO[jd][1] * inv0, hw, lw);
        ao_hi[row0 * 512 + w] = hw;
        ao_lo[row0 * 512 + w] = lw;
        split2(accO[jd][2] * inv1, accO[jd][3] * inv1, hw, lw);
        ao_hi[row1 * 512 + w] = hw;
        ao_lo[row1 * 512 + w] = lw;
    }
}

extern "C" void kernel_launch(void* const* d_in, const int* in_sizes, int n_in,
                              void* d_out, int out_size)
{
    const float* query = (const float*)d_in[0];
    const float* key   = (const float*)d_in[1];
    const float* value = (const float*)d_in[2];
    const unsigned char* mask = (const unsigned char*)d_in[3];
    const float* q_w = (const float*)d_in[4];
    const float* q_b = (const float*)d_in[5];
    const float* k_w = (const float*)d_in[6];
    const float* k_b = (const float*)d_in[7];
    const float* v_w = (const float*)d_in[8];
    const float* v_b = (const float*)d_in[9];
    const float* o_w = (const float*)d_in[10];
    const float* o_b = (const float*)d_in[11];
    const float* rel = (const float*)d_in[12];
    float* out = (float*)d_out;

    const int GSMEM = 81920;
    cudaFuncSetAttribute(proj_qkv, cudaFuncAttributeMaxDynamicSharedMemorySize, GSMEM);
    cudaFuncSetAttribute(proj_o,   cudaFuncAttributeMaxDynamicSharedMemorySize, GSMEM);
    cudaFuncSetAttribute(flash_attn, cudaFuncAttributeMaxDynamicSharedMemorySize, 73728);

    // One merged split launch: 3*NA4 + 4*NW4 = 4194304 float4 tasks
    const int nTot = 3 * NA4 + 4 * NW4;
    split_all<<<nTot / 256, 256>>>((const float4*)query, (const float4*)key,
                                   (const float4*)value, (const float4*)q_w,
                                   (const float4*)k_w,   (const float4*)v_w,
                                   (const float4*)o_w);

    // Merged Q/K/V projections: one 768-block launch
    dim3 pg(E_ / 128, (B_ * T_) / 128, 3);
    proj_qkv<<<pg, 256, GSMEM>>>(q_b, k_b, v_b, rel);

    dim3 fg(T_ / 128, B_ * H_, 1);
    flash_attn<<<fg, 256, 73728>>>(mask);

    dim3 og(E_ / 128, (B_ * T_) / 128, 1);
    proj_o<<<og, 256, GSMEM>>>(o_b, out);
}

// round 11
// speedup vs baseline: 3.0540x; 1.0044x over previous
#include <cuda_runtime.h>
#include <cuda_bf16.h>
#include <math.h>
#include <stdint.h>

#define B_ 4
#define T_ 1024
#define S_ 1024
#define E_ 1024
#define H_ 16
#define D_ 64
#define MAXLEN 2048

// ---------------- Pre-split bf16-pair device globals ----------------
// Activations [4096][512] pair-words (pairs along K)
__device__ uint32_t qa_hi[4096 * 512], qa_lo[4096 * 512];
__device__ uint32_t ka_hi[4096 * 512], ka_lo[4096 * 512];
__device__ uint32_t va_hi[4096 * 512], va_lo[4096 * 512];
__device__ uint32_t ao_hi[4096 * 512], ao_lo[4096 * 512];   // attention out (pair)
// Weights [1024][512]
__device__ uint32_t qw_hi[1024 * 512], qw_lo[1024 * 512];
__device__ uint32_t kw_hi[1024 * 512], kw_lo[1024 * 512];
__device__ uint32_t vw_hi[1024 * 512], vw_lo[1024 * 512];
__device__ uint32_t ow_hi[1024 * 512], ow_lo[1024 * 512];
// Projected q/k/v: [z][t][32] pair-words (pairs along d), z = b*16+h
__device__ uint32_t gq_hi[64 * 1024 * 32], gq_lo[64 * 1024 * 32];
__device__ uint32_t gk_hi[64 * 1024 * 32], gk_lo[64 * 1024 * 32];
__device__ uint32_t gv_hi[64 * 1024 * 32], gv_lo[64 * 1024 * 32];

__device__ __forceinline__ float neg_big() { return -1e30f; }

__device__ __forceinline__ void split2(float x, float y, uint32_t& hi, uint32_t& lo) {
    __nv_bfloat16 xh = __float2bfloat16(x);
    __nv_bfloat16 yh = __float2bfloat16(y);
    __nv_bfloat16 xl = __float2bfloat16(x - __bfloat162float(xh));
    __nv_bfloat16 yl = __float2bfloat16(y - __bfloat162float(yh));
    hi = (uint32_t)__bfloat16_as_ushort(xh) | ((uint32_t)__bfloat16_as_ushort(yh) << 16);
    lo = (uint32_t)__bfloat16_as_ushort(xl) | ((uint32_t)__bfloat16_as_ushort(yl) << 16);
}

__device__ __forceinline__ void mma_bf16(float c[4], const uint32_t a[4], const uint32_t b[2]) {
    asm volatile(
        "mma.sync.aligned.m16n8k16.row.col.f32.bf16.bf16.f32 "
        "{%0,%1,%2,%3}, {%4,%5,%6,%7}, {%8,%9}, {%0,%1,%2,%3};"
        : "+f"(c[0]), "+f"(c[1]), "+f"(c[2]), "+f"(c[3])
        : "r"(a[0]), "r"(a[1]), "r"(a[2]), "r"(a[3]), "r"(b[0]), "r"(b[1]));
}

__device__ __forceinline__ void ldmat_x4(uint32_t r[4], uint32_t addr) {
    asm volatile("ldmatrix.sync.aligned.m8n8.x4.shared.b16 {%0,%1,%2,%3}, [%4];"
                 : "=r"(r[0]), "=r"(r[1]), "=r"(r[2]), "=r"(r[3]) : "r"(addr));
}
__device__ __forceinline__ void ldmat_x2(uint32_t& r0, uint32_t& r1, uint32_t addr) {
    asm volatile("ldmatrix.sync.aligned.m8n8.x2.shared.b16 {%0,%1}, [%2];"
                 : "=r"(r0), "=r"(r1) : "r"(addr));
}
__device__ __forceinline__ void ldmat_x2_trans(uint32_t& r0, uint32_t& r1, uint32_t addr) {
    asm volatile("ldmatrix.sync.aligned.m8n8.x2.trans.shared.b16 {%0,%1}, [%2];"
                 : "=r"(r0), "=r"(r1) : "r"(addr));
}
__device__ __forceinline__ void cpa16(uint32_t dst, const void* src) {
    asm volatile("cp.async.cg.shared.global [%0], [%1], 16;" :: "r"(dst), "l"(src));
}
template <int N>
__device__ __forceinline__ void cpa_wait() {
    asm volatile("cp.async.wait_group %0;" :: "n"(N) : "memory");
}
__device__ __forceinline__ void cpa_commit() {
    asm volatile("cp.async.commit_group;" ::: "memory");
}

// ---------------------------------------------------------------------------
// Merged split kernel with 4x ILP: each block covers 1024 consecutive float4
// (segment-uniform: every segment boundary is 1024-aligned), each thread does
// 4 coalesced float4 loads -> MLP 4.
// Segments: qa/ka/va (NA4 each), then qw/kw/vw/ow (NW4 each).
// ---------------------------------------------------------------------------
#define NA4 (4096 * 1024 / 4)
#define NW4 (1024 * 1024 / 4)
__global__ __launch_bounds__(256) void split_all(
    const float4* __restrict__ q,  const float4* __restrict__ k,
    const float4* __restrict__ v,  const float4* __restrict__ qw,
    const float4* __restrict__ kw, const float4* __restrict__ vw,
    const float4* __restrict__ ow)
{
    int i0 = blockIdx.x * 1024;
    const float4* src;
    uint2 *hi, *lo;
    int li0 = i0;
    if (li0 < 3 * NA4) {
        int seg = li0 / NA4; li0 -= seg * NA4;
        src = (seg == 0) ? q : (seg == 1) ? k : v;
        hi = (uint2*)((seg == 0) ? qa_hi : (seg == 1) ? ka_hi : va_hi);
        lo = (uint2*)((seg == 0) ? qa_lo : (seg == 1) ? ka_lo : va_lo);
    } else {
        li0 -= 3 * NA4;
        int seg = li0 / NW4; li0 -= seg * NW4;
        src = (seg == 0) ? qw : (seg == 1) ? kw : (seg == 2) ? vw : ow;
        hi = (uint2*)((seg == 0) ? qw_hi : (seg == 1) ? kw_hi : (seg == 2) ? vw_hi : ow_hi);
        lo = (uint2*)((seg == 0) ? qw_lo : (seg == 1) ? kw_lo : (seg == 2) ? vw_lo : ow_lo);
    }
    float4 f[4];
#pragma unroll
    for (int c = 0; c < 4; c++) f[c] = src[li0 + threadIdx.x + c * 256];
#pragma unroll
    for (int c = 0; c < 4; c++) {
        int li = li0 + threadIdx.x + c * 256;
        uint32_t h0, l0, h1, l1;
        split2(f[c].x, f[c].y, h0, l0);
        split2(f[c].z, f[c].w, h1, l1);
        hi[li] = make_uint2(h0, h1);
        lo[li] = make_uint2(l0, l1);
    }
}

// ---------------------------------------------------------------------------
// GEMM mainloop shared by the two GEMM kernels (unchanged from R10).
// ---------------------------------------------------------------------------
#define GEMM_BODY(Ah, Al, Bh, Bl, K)                                              \
    const int lane = tid & 31, warp = tid >> 5;                                   \
    const int wy = warp >> 2, wx = warp & 3;                                      \
    const int grp = lane >> 2, tig = lane & 3;                                    \
    const int K2 = (K) >> 1;                                                      \
    uint32_t sbase;                                                               \
    asm("{.reg .u64 t; cvta.to.shared.u64 t, %1; cvt.u32.u64 %0, t;}"             \
        : "=r"(sbase) : "l"(dsm));                                                \
    float acc[4][4][4];                                                           \
    _Pragma("unroll")                                                             \
    for (int i = 0; i < 4; i++)                                                   \
        _Pragma("unroll")                                                         \
        for (int j = 0; j < 4; j++)                                               \
            _Pragma("unroll")                                                     \
            for (int r = 0; r < 4; r++) acc[i][j][r] = 0.0f;                      \
    const int nT = (K) / 32;                                                      \
    const uint32_t aA = (uint32_t)((wy * 64 + (lane & 15)) * 80 + (lane >> 4) * 16);       \
    const uint32_t aB = (uint32_t)(40960 + (wx * 32 + (lane & 7)) * 80 + ((lane >> 3) & 1) * 16); \
    {                                                                             \
        _Pragma("unroll")                                                         \
        for (int l = 0; l < 2; l++) {                                             \
            int idx = tid + l * 256;                                              \
            int row = idx >> 2, c4 = idx & 3;                                     \
            uint32_t off = (uint32_t)(row * 80 + c4 * 16);                        \
            size_t sA = (size_t)(m0 + row) * K2 + c4 * 4;                         \
            size_t sB = (size_t)(n0 + row) * K2 + c4 * 4;                         \
            cpa16(sbase + off,         (Ah) + sA);                                \
            cpa16(sbase + 20480 + off, (Al) + sA);                                \
            cpa16(sbase + 40960 + off, (Bh) + sB);                                \
            cpa16(sbase + 61440 + off, (Bl) + sB);                                \
        }                                                                         \
        cpa_commit();                                                             \
    }                                                                             \
    for (int t = 0; t < nT; t++) {                                                \
        const int st = t & 1;                                                     \
        if (t + 1 < nT) {                                                         \
            _Pragma("unroll")                                                     \
            for (int l = 0; l < 2; l++) {                                         \
                int idx = tid + l * 256;                                          \
                int row = idx >> 2, c4 = idx & 3;                                 \
                uint32_t off = (uint32_t)((st ^ 1) * 10240 + row * 80 + c4 * 16); \
                size_t sA = (size_t)(m0 + row) * K2 + (t + 1) * 16 + c4 * 4;      \
                size_t sB = (size_t)(n0 + row) * K2 + (t + 1) * 16 + c4 * 4;      \
                cpa16(sbase + off,         (Ah) + sA);                            \
                cpa16(sbase + 20480 + off, (Al) + sA);                            \
                cpa16(sbase + 40960 + off, (Bh) + sB);                            \
                cpa16(sbase + 61440 + off, (Bl) + sB);                            \
            }                                                                     \
            cpa_commit();                                                         \
            cpa_wait<1>();                                                        \
        } else {                                                                  \
            cpa_wait<0>();                                                        \
        }                                                                         \
        __syncthreads();                                                          \
        const uint32_t sb = sbase + st * 10240;                                   \
        _Pragma("unroll")                                                         \
        for (int ks = 0; ks < 2; ks++) {                                          \
            uint32_t bh[4][2], bl[4][2];                                          \
            _Pragma("unroll")                                                     \
            for (int j = 0; j < 4; j++) {                                         \
                ldmat_x2(bh[j][0], bh[j][1], sb + aB + j * 640 + ks * 32);        \
                ldmat_x2(bl[j][0], bl[j][1], sb + aB + 20480 + j * 640 + ks * 32);\
            }                                                                     \
            _Pragma("unroll")                                                     \
            for (int i = 0; i < 4; i++) {                                         \
                uint32_t ah[4], al[4];                                            \
                ldmat_x4(ah, sb + aA + i * 1280 + ks * 32);                       \
                ldmat_x4(al, sb + aA + 20480 + i * 1280 + ks * 32);               \
                _Pragma("unroll")                                                 \
                for (int j = 0; j < 4; j++) {                                     \
                    mma_bf16(acc[i][j], ah, bh[j]);                               \
                    mma_bf16(acc[i][j], al, bh[j]);                               \
                    mma_bf16(acc[i][j], ah, bl[j]);                               \
                }                                                                 \
            }                                                                     \
        }                                                                         \
        __syncthreads();                                                          \
    }

// ---------------------------------------------------------------------------
// Merged Q/K/V projection GEMM: blockIdx.z in {0,1,2} selects the projection.
// ---------------------------------------------------------------------------
__global__ __launch_bounds__(256, 2) void proj_qkv(
    const float* __restrict__ q_b, const float* __restrict__ k_b,
    const float* __restrict__ v_b, const float* __restrict__ rel)
{
    extern __shared__ uint32_t dsm[];
    const int which = blockIdx.z;
    const int tid = threadIdx.x;
    const int m0 = blockIdx.y * 128;
    const int n0 = blockIdx.x * 128;

    const uint32_t* Ah = (which == 0) ? qa_hi : (which == 1) ? ka_hi : va_hi;
    const uint32_t* Al = (which == 0) ? qa_lo : (which == 1) ? ka_lo : va_lo;
    const uint32_t* Bh = (which == 0) ? qw_hi : (which == 1) ? kw_hi : vw_hi;
    const uint32_t* Bl = (which == 0) ? qw_lo : (which == 1) ? kw_lo : vw_lo;
    const float* bias  = (which == 0) ? q_b : (which == 1) ? k_b : v_b;
    uint32_t* Dh = (which == 0) ? gq_hi : (which == 1) ? gk_hi : gv_hi;
    uint32_t* Dl = (which == 0) ? gq_lo : (which == 1) ? gk_lo : gv_lo;

    GEMM_BODY(Ah, Al, Bh, Bl, E_)

#pragma unroll
    for (int i = 0; i < 4; i++) {
        int mrow = m0 + wy * 64 + i * 16 + grp;
#pragma unroll
        for (int j = 0; j < 4; j++) {
            int ne = n0 + wx * 32 + j * 8 + 2 * tig;
            int h = ne >> 6, dl = ne & 63, dw = dl >> 1;
            float b0 = bias[ne], b1 = bias[ne + 1];
#pragma unroll
            for (int half = 0; half < 2; half++) {
                int m = mrow + half * 8;
                int bb = m >> 10, tt = m & 1023;
                float v0 = acc[i][j][2 * half]     + b0;
                float v1 = acc[i][j][2 * half + 1] + b1;
                if (which == 1) {
                    v0 += rel[((size_t)h * MAXLEN + tt) * D_ + dl];
                    v1 += rel[((size_t)h * MAXLEN + tt) * D_ + dl + 1];
                }
                uint32_t hw, lw;
                split2(v0, v1, hw, lw);
                size_t di = ((size_t)(bb * H_ + h) * T_ + tt) * 32 + dw;
                Dh[di] = hw;
                Dl[di] = lw;
            }
        }
    }
}

// ---------------------------------------------------------------------------
// O projection GEMM: ao_pair @ ow_pair^T + bias -> fp32 out
// ---------------------------------------------------------------------------
__global__ __launch_bounds__(256, 2) void proj_o(
    const float* __restrict__ bias, float* __restrict__ out)
{
    extern __shared__ uint32_t dsm[];
    const int tid = threadIdx.x;
    const int m0 = blockIdx.y * 128;
    const int n0 = blockIdx.x * 128;

    GEMM_BODY(ao_hi, ao_lo, ow_hi, ow_lo, E_)

#pragma unroll
    for (int i = 0; i < 4; i++) {
        int mrow = m0 + wy * 64 + i * 16 + grp;
#pragma unroll
        for (int j = 0; j < 4; j++) {
            int ne = n0 + wx * 32 + j * 8 + 2 * tig;
            float b0 = bias[ne], b1 = bias[ne + 1];
            out[(size_t)mrow * E_ + ne]           = acc[i][j][0] + b0;
            out[(size_t)mrow * E_ + ne + 1]       = acc[i][j][1] + b1;
            out[(size_t)(mrow + 8) * E_ + ne]     = acc[i][j][2] + b0;
            out[(size_t)(mrow + 8) * E_ + ne + 1] = acc[i][j][3] + b1;
        }
    }
}

// ---------------------------------------------------------------------------
// Fused flash attention, K/V double-buffered (2-stage cp.async).
// Smem layout (u32 words):
//   Qhi @0 (4608), Qlo @4608
//   stage0: Khi @9216, Klo @11520, Vhi @13824, Vlo @16128
//   stage1: Khi @18432, Klo @20736, Vhi @23040, Vlo @25344
// Total 27648 words = 110592 B; x2 CTAs = 221184 B < 228 KB.
// ---------------------------------------------------------------------------
__global__ __launch_bounds__(256, 2) void flash_attn(const unsigned char* __restrict__ mask)
{
    extern __shared__ uint32_t sm[];
    uint32_t* Qhi = sm;
    uint32_t* Qlo = sm + 4608;

    const int tid = threadIdx.x;
    const int lane = tid & 31, warp = tid >> 5;
    const int grp = lane >> 2, tig = lane & 3;
    const int m0 = blockIdx.x * 128;
    const int z  = blockIdx.y;
    const int bb = z >> 4, h = z & 15;

    const unsigned char* mrow_g = mask + (size_t)bb * S_;

    uint32_t sbase;
    asm("{.reg .u64 t; cvta.to.shared.u64 t, %1; cvt.u32.u64 %0, t;}"
        : "=r"(sbase) : "l"(sm));
    const uint32_t vrow0 = sbase + 55296 + (lane & 15) * 144;   // Vhi stage0 row base

    // Q fill (cp.async): 128 rows x 32 words (hi + lo)
#pragma unroll
    for (int l = 0; l < 4; l++) {
        int idx = tid + l * 256;
        int row = idx >> 3, c4 = idx & 7;
        uint32_t off = (uint32_t)(row * 144 + c4 * 16);
        size_t src = ((size_t)z * T_ + m0 + row) * 32 + c4 * 4;
        cpa16(sbase + off,         gq_hi + src);
        cpa16(sbase + 18432 + off, gq_lo + src);
    }

    // K/V fill for stage sg of s-tile tt (64 rows x 32 words each, hi+lo)
#define KVFILL(tt, sg)                                                            \
    {                                                                             \
        uint32_t sgo = (uint32_t)(sg) * 36864;                                    \
        _Pragma("unroll")                                                         \
        for (int l = 0; l < 2; l++) {                                             \
            int idx = tid + l * 256;                                              \
            int row = idx >> 3, c4 = idx & 7;                                     \
            uint32_t off = sgo + (uint32_t)(row * 144 + c4 * 16);                 \
            size_t src = ((size_t)z * S_ + (tt) * 64 + row) * 32 + c4 * 4;        \
            cpa16(sbase + 36864 + off, gk_hi + src);                              \
            cpa16(sbase + 46080 + off, gk_lo + src);                              \
            cpa16(sbase + 55296 + off, gv_hi + src);                              \
            cpa16(sbase + 64512 + off, gv_lo + src);                              \
        }                                                                         \
        cpa_commit();                                                             \
    }

    float accO[8][4];
#pragma unroll
    for (int jd = 0; jd < 8; jd++)
#pragma unroll
        for (int r = 0; r < 4; r++) accO[jd][r] = 0.0f;
    float m0r = -1e29f, m1r = -1e29f, l0r = 0.0f, l1r = 0.0f;

    const int r0 = warp * 16 + grp;

    KVFILL(0, 0);   // commits Q loads together with tile 0

    for (int t = 0; t < S_ / 64; t++) {
        const int st = t & 1;
        const int s0 = t * 64;
        if (t + 1 < S_ / 64) { KVFILL(t + 1, st ^ 1); cpa_wait<1>(); }
        else                 { cpa_wait<0>(); }
        __syncthreads();

        const uint32_t* KhiS = sm + 9216 + st * 9216;
        const uint32_t* KloS = sm + 11520 + st * 9216;
        const uint32_t vrow_h = vrow0 + st * 36864;

        // Scores: warp's 16 rows x 64 cols, bf16x3
        float acc[8][4];
#pragma unroll
        for (int j = 0; j < 8; j++)
#pragma unroll
            for (int r = 0; r < 4; r++) acc[j][r] = 0.0f;

#pragma unroll
        for (int ks = 0; ks < 4; ks++) {
            const int kb = ks * 8;
            uint32_t qh[4], ql[4];
            qh[0] = Qhi[r0 * 36 + kb + tig];
            qh[1] = Qhi[(r0 + 8) * 36 + kb + tig];
            qh[2] = Qhi[r0 * 36 + kb + tig + 4];
            qh[3] = Qhi[(r0 + 8) * 36 + kb + tig + 4];
            ql[0] = Qlo[r0 * 36 + kb + tig];
            ql[1] = Qlo[(r0 + 8) * 36 + kb + tig];
            ql[2] = Qlo[r0 * 36 + kb + tig + 4];
            ql[3] = Qlo[(r0 + 8) * 36 + kb + tig + 4];
#pragma unroll
            for (int j = 0; j < 8; j++) {
                int c0 = j * 8 + grp;
                uint32_t kh[2], kl[2];
                kh[0] = KhiS[c0 * 36 + kb + tig];
                kh[1] = KhiS[c0 * 36 + kb + tig + 4];
                kl[0] = KloS[c0 * 36 + kb + tig];
                kl[1] = KloS[c0 * 36 + kb + tig + 4];
                mma_bf16(acc[j], qh, kh);
                mma_bf16(acc[j], ql, kh);
                mma_bf16(acc[j], qh, kl);
            }
        }

        // Mask
#pragma unroll
        for (int j = 0; j < 8; j++) {
            int c = s0 + j * 8 + 2 * tig;
            if (mrow_g[c])     { acc[j][0] = neg_big(); acc[j][2] = neg_big(); }
            if (mrow_g[c + 1]) { acc[j][1] = neg_big(); acc[j][3] = neg_big(); }
        }

        // Online softmax
        float tm0 = neg_big(), tm1 = neg_big();
#pragma unroll
        for (int j = 0; j < 8; j++) {
            tm0 = fmaxf(tm0, fmaxf(acc[j][0], acc[j][1]));
            tm1 = fmaxf(tm1, fmaxf(acc[j][2], acc[j][3]));
        }
        tm0 = fmaxf(tm0, __shfl_xor_sync(0xffffffffu, tm0, 1));
        tm0 = fmaxf(tm0, __shfl_xor_sync(0xffffffffu, tm0, 2));
        tm1 = fmaxf(tm1, __shfl_xor_sync(0xffffffffu, tm1, 1));
        tm1 = fmaxf(tm1, __shfl_xor_sync(0xffffffffu, tm1, 2));

        float mn0 = fmaxf(fmaxf(m0r, tm0), -1e29f);
        float mn1 = fmaxf(fmaxf(m1r, tm1), -1e29f);
        float sc0 = __expf(m0r - mn0);
        float sc1 = __expf(m1r - mn1);

        float ts0 = 0.0f, ts1 = 0.0f;
#pragma unroll
        for (int j = 0; j < 8; j++) {
            acc[j][0] = __expf(acc[j][0] - mn0);
            acc[j][1] = __expf(acc[j][1] - mn0);
            acc[j][2] = __expf(acc[j][2] - mn1);
            acc[j][3] = __expf(acc[j][3] - mn1);
            ts0 += acc[j][0] + acc[j][1];
            ts1 += acc[j][2] + acc[j][3];
        }
        ts0 += __shfl_xor_sync(0xffffffffu, ts0, 1);
        ts0 += __shfl_xor_sync(0xffffffffu, ts0, 2);
        ts1 += __shfl_xor_sync(0xffffffffu, ts1, 1);
        ts1 += __shfl_xor_sync(0xffffffffu, ts1, 2);

        l0r = l0r * sc0 + ts0;
        l1r = l1r * sc1 + ts1;
        m0r = mn0; m1r = mn1;

#pragma unroll
        for (int jd = 0; jd < 8; jd++) {
            accO[jd][0] *= sc0; accO[jd][1] *= sc0;
            accO[jd][2] *= sc1; accO[jd][3] *= sc1;
        }

        // PV: register-split probs @ V (ldmatrix.trans), bf16x3
#pragma unroll
        for (int ks = 0; ks < 4; ks++) {
            uint32_t ah[4], al[4];
            split2(acc[2 * ks][0],     acc[2 * ks][1],     ah[0], al[0]);
            split2(acc[2 * ks][2],     acc[2 * ks][3],     ah[1], al[1]);
            split2(acc[2 * ks + 1][0], acc[2 * ks + 1][1], ah[2], al[2]);
            split2(acc[2 * ks + 1][2], acc[2 * ks + 1][3], ah[3], al[3]);
            uint32_t rbase = vrow_h + ks * 2304;
#pragma unroll
            for (int jd = 0; jd < 8; jd++) {
                uint32_t bh[2], bl[2];
                ldmat_x2_trans(bh[0], bh[1], rbase + jd * 16);
                ldmat_x2_trans(bl[0], bl[1], rbase + jd * 16 + 9216);
                mma_bf16(accO[jd], ah, bh);
                mma_bf16(accO[jd], al, bh);
                mma_bf16(accO[jd], ah, bl);
            }
        }
        __syncthreads();
    }
#undef KVFILL

    // Epilogue: normalized O -> ao pair arrays [4096][512]
    float inv0 = 1.0f / l0r, inv1 = 1.0f / l1r;
    size_t row0 = (size_t)bb * T_ + m0 + warp * 16 + grp;
    size_t row1 = row0 + 8;
#pragma unroll
    for (int jd = 0; jd < 8; jd++) {
        int w = h * 32 + jd * 4 + tig;
        uint32_t hw, lw;
        split2(accO[jd][0] * inv0, accO[jd][1] * inv0, hw, lw);
        ao_hi[row0 * 512 + w] = hw;
        ao_lo[row0 * 512 + w] = lw;
        split2(accO[jd][2] * inv1, accO[jd][3] * inv1, hw, lw);
        ao_hi[row1 * 512 + w] = hw;
        ao_lo[row1 * 512 + w] = lw;
    }
}

extern "C" void kernel_launch(void* const* d_in, const int* in_sizes, int n_in,
                              void* d_out, int out_size)
{
    const float* query = (const float*)d_in[0];
    const float* key   = (const float*)d_in[1];
    const float* value = (const float*)d_in[2];
    const unsigned char* mask = (const unsigned char*)d_in[3];
    const float* q_w = (const float*)d_in[4];
    const float* q_b = (const float*)d_in[5];
    const float* k_w = (const float*)d_in[6];
    const float* k_b = (const float*)d_in[7];
    const float* v_w = (const float*)d_in[8];
    const float* v_b = (const float*)d_in[9];
    const float* o_w = (const float*)d_in[10];
    const float* o_b = (const float*)d_in[11];
    const float* rel = (const float*)d_in[12];
    float* out = (float*)d_out;

    const int GSMEM = 81920;
    const int FSMEM = 110592;
    cudaFuncSetAttribute(proj_qkv, cudaFuncAttributeMaxDynamicSharedMemorySize, GSMEM);
    cudaFuncSetAttribute(proj_o,   cudaFuncAttributeMaxDynamicSharedMemorySize, GSMEM);
    cudaFuncSetAttribute(flash_attn, cudaFuncAttributeMaxDynamicSharedMemorySize, FSMEM);

    // Merged split launch: 4x ILP, 1024 float4 per block
    const int nTot = 3 * NA4 + 4 * NW4;
    split_all<<<nTot / 1024, 256>>>((const float4*)query, (const float4*)key,
                                    (const float4*)value, (const float4*)q_w,
                                    (const float4*)k_w,   (const float4*)v_w,
                                    (const float4*)o_w);

    // Merged Q/K/V projections
    dim3 pg(E_ / 128, (B_ * T_) / 128, 3);
    proj_qkv<<<pg, 256, GSMEM>>>(q_b, k_b, v_b, rel);

    dim3 fg(T_ / 128, B_ * H_, 1);
    flash_attn<<<fg, 256, FSMEM>>>(mask);

    dim3 og(E_ / 128, (B_ * T_) / 128, 1);
    proj_o<<<og, 256, GSMEM>>>(o_b, out);
}